// round 1
// baseline (speedup 1.0000x reference)
#include <cuda_runtime.h>
#include <math.h>

#define NATOMS 25000
#define NEDGES 300000
#define NGRAPH 500
#define DDIM   256
#define ADIM   200
#define LLAYERS 3
#define TE     32      // rows (edges/atoms) per block tile
#define PADR   34      // smem row stride (k-major), even => 8B-aligned pairs, low bank conflict

// COEF = e^2 / (4 pi eps0 1e-10), rounded to f32 like the reference
#define COEF_F ((float)(1.602176634e-19 * 1.602176634e-19 / \
                 (4.0 * 3.14159265358979323846 * 8.8541878128e-12 * 1e-10)))

// ---- scratch (static device globals; no allocation) ----
__device__ float d_dist[NEDGES];
__device__ float d_h   [NATOMS * DDIM];
__device__ float d_hsrc[NATOMS * DDIM];
__device__ float d_hdst[NATOMS * DDIM];
__device__ float d_agg [NATOMS * DDIM];
__device__ float d_pool[NGRAPH];
__device__ int   d_cnt [NGRAPH];

// ---- packed f32x2 helpers ----
__device__ __forceinline__ unsigned long long pack2f(float lo, float hi) {
    unsigned long long v;
    asm("mov.b64 %0, {%1, %2};" : "=l"(v) : "f"(lo), "f"(hi));
    return v;
}
__device__ __forceinline__ void unpack2f(unsigned long long v, float& lo, float& hi) {
    asm("mov.b64 {%0, %1}, %2;" : "=f"(lo), "=f"(hi) : "l"(v));
}
__device__ __forceinline__ void fma2(unsigned long long& a, unsigned long long x, unsigned long long w) {
    asm("fma.rn.f32x2 %0, %1, %2, %0;" : "+l"(a) : "l"(x), "l"(w));
}

__device__ __forceinline__ float softplus_f(float x) {
    // matches jax.nn.softplus: max(x,0) + log1p(exp(-|x|))
    return fmaxf(x, 0.0f) + log1pf(expf(-fabsf(x)));
}
__device__ __forceinline__ float mish_f(float x) {
    return x * tanhf(softplus_f(x));
}

// Core tile GEMM: out[r][d] = sum_k xs[k*PADR + r] * W[k*256 + d]
// 256 threads, thread d owns output column d for all TE=32 rows (16 row-pairs).
// Inner loop: LDS.64 (row pair, broadcast) + FFMA2, 8-deep LDG prefetch of W.
__device__ __forceinline__ void gemm32(const float* __restrict__ W,
                                       const float* __restrict__ xs,
                                       int K, int d, unsigned long long acc[16]) {
#pragma unroll
    for (int j = 0; j < 16; j++) acc[j] = 0ULL;
    for (int k0 = 0; k0 < K; k0 += 8) {
        float w[8];
#pragma unroll
        for (int i = 0; i < 8; i++) w[i] = W[(size_t)(k0 + i) * DDIM + d];
#pragma unroll
        for (int i = 0; i < 8; i++) {
            unsigned long long wv = pack2f(w[i], w[i]);
            const unsigned long long* xr =
                (const unsigned long long*)(xs + (size_t)(k0 + i) * PADR);
#pragma unroll
            for (int j = 0; j < 16; j++) fma2(acc[j], xr[j], wv);
        }
    }
}

// ---- small kernels ----
__global__ void __launch_bounds__(256) dist_kernel(const float* __restrict__ r) {
    int e = blockIdx.x * blockDim.x + threadIdx.x;
    if (e < NEDGES) {
        float x = r[3 * e], y = r[3 * e + 1], z = r[3 * e + 2];
        d_dist[e] = sqrtf(x * x + y * y + z * z);
    }
}

__global__ void __launch_bounds__(256) zero_agg_kernel() {
    int i = blockIdx.x * blockDim.x + threadIdx.x;
    if (i < NATOMS * DDIM) d_agg[i] = 0.0f;
}

__global__ void __launch_bounds__(256) softplus_kernel() {
    int i = blockIdx.x * blockDim.x + threadIdx.x;
    if (i < NATOMS * DDIM) d_h[i] = softplus_f(d_h[i] + d_agg[i]);
}

__global__ void __launch_bounds__(256) zero_pool_kernel() {
    int g = blockIdx.x * blockDim.x + threadIdx.x;
    if (g < NGRAPH) { d_pool[g] = 0.0f; d_cnt[g] = 0; }
}

__global__ void __launch_bounds__(256) pool_kernel(const int* __restrict__ gids,
                                                   const float* __restrict__ out_w) {
    int warp = (blockIdx.x * blockDim.x + threadIdx.x) >> 5;
    int lane = threadIdx.x & 31;
    if (warp >= NATOMS) return;
    float s = 0.0f;
    for (int k = lane; k < DDIM; k += 32)
        s += d_h[(size_t)warp * DDIM + k] * out_w[k];
#pragma unroll
    for (int off = 16; off > 0; off >>= 1)
        s += __shfl_xor_sync(0xFFFFFFFFu, s, off);
    if (lane == 0) {
        atomicAdd(&d_pool[gids[warp]], s);
        atomicAdd(&d_cnt[gids[warp]], 1);
    }
}

__global__ void __launch_bounds__(256) final_kernel(const float* __restrict__ out_b,
                                                    float* __restrict__ out) {
    int g = blockIdx.x * blockDim.x + threadIdx.x;
    if (g < NGRAPH)
        out[g] = d_pool[g] / fmaxf((float)d_cnt[g], 1.0f) + out_b[0];
}

// ---- embedding: h = af_table[atom_types] @ emb_w + emb_b ----
__global__ void __launch_bounds__(256) embed_kernel(const int* __restrict__ atom_types,
                                                    const float* __restrict__ af,
                                                    const float* __restrict__ emb_w,
                                                    const float* __restrict__ emb_b) {
    extern __shared__ float sm[];
    float* xa = sm;  // [ADIM][PADR] k-major
    __shared__ int sT[TE];
    int tid = threadIdx.x, d = tid;
    int row0 = blockIdx.x * TE;
    if (tid < TE) {
        int row = row0 + tid;
        sT[tid] = (row < NATOMS) ? atom_types[row] : 0;
    }
    __syncthreads();
    for (int idx = tid; idx < TE * ADIM; idx += 256) {
        int r = idx / ADIM, k = idx - r * ADIM;
        xa[k * PADR + r] = (row0 + r < NATOMS) ? af[(size_t)sT[r] * ADIM + k] : 0.0f;
    }
    __syncthreads();
    unsigned long long acc[16];
    gemm32(emb_w, xa, ADIM, d, acc);
    float b = emb_b[d];
#pragma unroll
    for (int j = 0; j < 16; j++) {
        float lo, hi; unpack2f(acc[j], lo, hi);
        int r0 = 2 * j, r1 = 2 * j + 1;
        if (row0 + r0 < NATOMS) d_h[(size_t)(row0 + r0) * DDIM + d] = lo + b;
        if (row0 + r1 < NATOMS) d_h[(size_t)(row0 + r1) * DDIM + d] = hi + b;
    }
}

// ---- node kernel: both src/dst 2-layer MLPs from one h tile ----
__global__ void __launch_bounds__(256) node_kernel(
    const float* __restrict__ W1s, const float* __restrict__ b1s,
    const float* __restrict__ W2s, const float* __restrict__ b2s,
    const float* __restrict__ W1d, const float* __restrict__ b1d,
    const float* __restrict__ W2d, const float* __restrict__ b2d) {
    extern __shared__ float sm[];
    float* xa = sm;          // input tile   [256][PADR]
    float* xb = sm + 8704;   // hidden tile  [256][PADR]
    int tid = threadIdx.x, d = tid;
    int row0 = blockIdx.x * TE;
    for (int idx = tid; idx < TE * DDIM; idx += 256) {
        int r = idx >> 8, k = idx & 255;
        int row = row0 + r;
        xa[k * PADR + r] = (row < NATOMS) ? d_h[(size_t)row * DDIM + k] : 0.0f;
    }
    __syncthreads();
    unsigned long long acc[16];

    // src branch
    gemm32(W1s, xa, DDIM, d, acc);
    {
        float b = b1s[d];
#pragma unroll
        for (int j = 0; j < 16; j++) {
            float lo, hi; unpack2f(acc[j], lo, hi);
            xb[d * PADR + 2 * j]     = mish_f(lo + b);
            xb[d * PADR + 2 * j + 1] = mish_f(hi + b);
        }
    }
    __syncthreads();
    gemm32(W2s, xb, DDIM, d, acc);
    {
        float b = b2s[d];
#pragma unroll
        for (int j = 0; j < 16; j++) {
            float lo, hi; unpack2f(acc[j], lo, hi);
            int r0 = 2 * j, r1 = 2 * j + 1;
            if (row0 + r0 < NATOMS) d_hsrc[(size_t)(row0 + r0) * DDIM + d] = lo + b;
            if (row0 + r1 < NATOMS) d_hsrc[(size_t)(row0 + r1) * DDIM + d] = hi + b;
        }
    }
    __syncthreads();

    // dst branch (xa still intact)
    gemm32(W1d, xa, DDIM, d, acc);
    {
        float b = b1d[d];
#pragma unroll
        for (int j = 0; j < 16; j++) {
            float lo, hi; unpack2f(acc[j], lo, hi);
            xb[d * PADR + 2 * j]     = mish_f(lo + b);
            xb[d * PADR + 2 * j + 1] = mish_f(hi + b);
        }
    }
    __syncthreads();
    gemm32(W2d, xb, DDIM, d, acc);
    {
        float b = b2d[d];
#pragma unroll
        for (int j = 0; j < 16; j++) {
            float lo, hi; unpack2f(acc[j], lo, hi);
            int r0 = 2 * j, r1 = 2 * j + 1;
            if (row0 + r0 < NATOMS) d_hdst[(size_t)(row0 + r0) * DDIM + d] = lo + b;
            if (row0 + r1 < NATOMS) d_hdst[(size_t)(row0 + r1) * DDIM + d] = hi + b;
        }
    }
}

// ---- fused edge kernel: RBF -> edge MLP -> Coulomb combine -> m MLP -> atomic agg ----
__global__ void __launch_bounds__(256) edge_kernel(
    const int* __restrict__ esrc, const int* __restrict__ edst,
    const float* __restrict__ W1e, const float* __restrict__ b1e,
    const float* __restrict__ W2e, const float* __restrict__ b2e,
    const float* __restrict__ W1m, const float* __restrict__ b1m,
    const float* __restrict__ W2m, const float* __restrict__ b2m) {
    extern __shared__ float sm[];
    float* xa = sm;
    float* xb = sm + 8704;
    __shared__ int   sSrc[TE], sDst[TE];
    __shared__ float sDist[TE];
    int tid = threadIdx.x, d = tid;
    int e0 = blockIdx.x * TE;
    if (tid < TE) {
        sSrc[tid]  = esrc[e0 + tid];
        sDst[tid]  = edst[e0 + tid];
        sDist[tid] = d_dist[e0 + tid];
    }
    __syncthreads();

    // RBF expansion into xa (thread d = RBF bin d, all 32 edges)
    {
        float c = (float)d * (1.0f / 255.0f);
#pragma unroll
        for (int r = 0; r < TE; r++) {
            float t = sDist[r] - c;
            xa[d * PADR + r] = expf(-255.0f * t * t);
        }
    }
    __syncthreads();

    unsigned long long acc[16];

    // edge MLP layer 1: hid = mish(ef @ W1e + b1e)
    gemm32(W1e, xa, DDIM, d, acc);
    {
        float b = b1e[d];
#pragma unroll
        for (int j = 0; j < 16; j++) {
            float lo, hi; unpack2f(acc[j], lo, hi);
            xb[d * PADR + 2 * j]     = mish_f(lo + b);
            xb[d * PADR + 2 * j + 1] = mish_f(hi + b);
        }
    }
    __syncthreads();

    // edge MLP layer 2 + Coulomb combine: hn = h_src*h_dst*COEF/e_lin
    gemm32(W2e, xb, DDIM, d, acc);
    {
        float b = b2e[d];
#pragma unroll
        for (int j = 0; j < 16; j++) {
            float lo, hi; unpack2f(acc[j], lo, hi);
            int r0 = 2 * j, r1 = 2 * j + 1;
            float hn0 = d_hsrc[(size_t)sSrc[r0] * DDIM + d] *
                        d_hdst[(size_t)sDst[r0] * DDIM + d] * COEF_F / (lo + b);
            float hn1 = d_hsrc[(size_t)sSrc[r1] * DDIM + d] *
                        d_hdst[(size_t)sDst[r1] * DDIM + d] * COEF_F / (hi + b);
            xa[d * PADR + r0] = hn0;
            xa[d * PADR + r1] = hn1;
        }
    }
    __syncthreads();

    // m MLP layer 1
    gemm32(W1m, xa, DDIM, d, acc);
    {
        float b = b1m[d];
#pragma unroll
        for (int j = 0; j < 16; j++) {
            float lo, hi; unpack2f(acc[j], lo, hi);
            xb[d * PADR + 2 * j]     = mish_f(lo + b);
            xb[d * PADR + 2 * j + 1] = mish_f(hi + b);
        }
    }
    __syncthreads();

    // m MLP layer 2 + segment-sum scatter
    gemm32(W2m, xb, DDIM, d, acc);
    {
        float b = b2m[d];
#pragma unroll
        for (int j = 0; j < 16; j++) {
            float lo, hi; unpack2f(acc[j], lo, hi);
            int r0 = 2 * j, r1 = 2 * j + 1;
            atomicAdd(&d_agg[(size_t)sDst[r0] * DDIM + d], lo + b);
            atomicAdd(&d_agg[(size_t)sDst[r1] * DDIM + d], hi + b);
        }
    }
}

extern "C" void kernel_launch(void* const* d_in, const int* in_sizes, int n_in,
                              void* d_out, int out_size) {
    const int*   atom_types = (const int*)  d_in[0];
    const int*   esrc       = (const int*)  d_in[1];
    const int*   edst       = (const int*)  d_in[2];
    const int*   gids       = (const int*)  d_in[3];
    const float* r          = (const float*)d_in[4];
    const float* af         = (const float*)d_in[5];
    const float* emb_w      = (const float*)d_in[6];
    const float* emb_b      = (const float*)d_in[7];
    const float* cw1        = (const float*)d_in[8];
    const float* cb1        = (const float*)d_in[9];
    const float* cw2        = (const float*)d_in[10];
    const float* cb2        = (const float*)d_in[11];
    const float* out_w      = (const float*)d_in[12];
    const float* out_b      = (const float*)d_in[13];
    float* out = (float*)d_out;

    const int SMEM_BIG   = 2 * 8704 * 4;   // 69632 B
    const int SMEM_EMBED = ADIM * PADR * 4;
    cudaFuncSetAttribute(edge_kernel,  cudaFuncAttributeMaxDynamicSharedMemorySize, SMEM_BIG);
    cudaFuncSetAttribute(node_kernel,  cudaFuncAttributeMaxDynamicSharedMemorySize, SMEM_BIG);
    cudaFuncSetAttribute(embed_kernel, cudaFuncAttributeMaxDynamicSharedMemorySize, SMEM_EMBED);

    dist_kernel<<<(NEDGES + 255) / 256, 256>>>(r);
    embed_kernel<<<(NATOMS + TE - 1) / TE, 256, SMEM_EMBED>>>(atom_types, af, emb_w, emb_b);

    const size_t MM = (size_t)DDIM * DDIM;
    for (int l = 0; l < LLAYERS; l++) {
        const float* W1 = cw1 + (size_t)l * 4 * MM;
        const float* B1 = cb1 + (size_t)l * 4 * DDIM;
        const float* W2 = cw2 + (size_t)l * 4 * MM;
        const float* B2 = cb2 + (size_t)l * 4 * DDIM;

        node_kernel<<<(NATOMS + TE - 1) / TE, 256, SMEM_BIG>>>(
            W1 + 0 * MM, B1 + 0 * DDIM, W2 + 0 * MM, B2 + 0 * DDIM,
            W1 + 1 * MM, B1 + 1 * DDIM, W2 + 1 * MM, B2 + 1 * DDIM);

        zero_agg_kernel<<<(NATOMS * DDIM + 255) / 256, 256>>>();

        edge_kernel<<<NEDGES / TE, 256, SMEM_BIG>>>(
            esrc, edst,
            W1 + 2 * MM, B1 + 2 * DDIM, W2 + 2 * MM, B2 + 2 * DDIM,
            W1 + 3 * MM, B1 + 3 * DDIM, W2 + 3 * MM, B2 + 3 * DDIM);

        softplus_kernel<<<(NATOMS * DDIM + 255) / 256, 256>>>();
    }

    zero_pool_kernel<<<(NGRAPH + 255) / 256, 256>>>();
    pool_kernel<<<(NATOMS * 32 + 255) / 256, 256>>>(gids, out_w);
    final_kernel<<<(NGRAPH + 255) / 256, 256>>>(out_b, out);
}

// round 2
// speedup vs baseline: 1.0335x; 1.0335x over previous
#include <cuda_runtime.h>
#include <math.h>

#define NATOMS 25000
#define NEDGES 300000
#define NGRAPH 500
#define DDIM   256
#define ADIM   200
#define LLAYERS 3
#define TE     32      // rows (edges/atoms) per block tile
#define PADR   36      // smem row stride (k-major): 144B, 16B-aligned for LDS.128

// COEF = e^2 / (4 pi eps0 1e-10), rounded to f32 like the reference
#define COEF_F ((float)(1.602176634e-19 * 1.602176634e-19 / \
                 (4.0 * 3.14159265358979323846 * 8.8541878128e-12 * 1e-10)))

// ---- scratch (static device globals; no allocation) ----
__device__ float d_dist[NEDGES];
__device__ float d_h   [NATOMS * DDIM];
__device__ float d_hsrc[NATOMS * DDIM];
__device__ float d_hdst[NATOMS * DDIM];
__device__ float d_agg [NATOMS * DDIM];
__device__ float d_pool[NGRAPH];
__device__ int   d_cnt [NGRAPH];

// ---- packed f32x2 helpers ----
__device__ __forceinline__ unsigned long long pack2f(float lo, float hi) {
    unsigned long long v;
    asm("mov.b64 %0, {%1, %2};" : "=l"(v) : "f"(lo), "f"(hi));
    return v;
}
__device__ __forceinline__ void unpack2f(unsigned long long v, float& lo, float& hi) {
    asm("mov.b64 {%0, %1}, %2;" : "=f"(lo), "=f"(hi) : "l"(v));
}
__device__ __forceinline__ void fma2(unsigned long long& a, unsigned long long x, unsigned long long w) {
    asm("fma.rn.f32x2 %0, %1, %2, %0;" : "+l"(a) : "l"(x), "l"(w));
}

__device__ __forceinline__ float softplus_f(float x) {
    return fmaxf(x, 0.0f) + __logf(1.0f + __expf(-fabsf(x)));
}
// mish(x) = x * tanh(softplus(x)) = x * (p^2-1)/(p^2+1), p = 1+e^x
__device__ __forceinline__ float mish_f(float x) {
    float ex = __expf(fminf(x, 20.0f));
    float p  = 1.0f + ex;
    float p2 = p * p;
    return x * __fdividef(p2 - 1.0f, p2 + 1.0f);
}

// Core tile GEMM: out[r][d] = sum_k xs[k*PADR + r] * W[k*256 + d]
// 256 threads, thread d owns output column d for all TE=32 rows (16 row-pairs).
// Inner loop per k: 8x LDS.128 (broadcast) + 16x FFMA2; W prefetched 8-deep via LDG.
__device__ __forceinline__ void gemm32(const float* __restrict__ W,
                                       const float* __restrict__ xs,
                                       int K, int d, unsigned long long acc[16]) {
#pragma unroll
    for (int j = 0; j < 16; j++) acc[j] = 0ULL;
    for (int k0 = 0; k0 < K; k0 += 8) {
        float w[8];
#pragma unroll
        for (int i = 0; i < 8; i++) w[i] = W[(size_t)(k0 + i) * DDIM + d];
#pragma unroll
        for (int i = 0; i < 8; i++) {
            unsigned long long wv = pack2f(w[i], w[i]);
            const ulonglong2* xr =
                (const ulonglong2*)(xs + (size_t)(k0 + i) * PADR);
#pragma unroll
            for (int j2 = 0; j2 < 8; j2++) {
                ulonglong2 v = xr[j2];
                fma2(acc[2 * j2],     v.x, wv);
                fma2(acc[2 * j2 + 1], v.y, wv);
            }
        }
    }
}

// ---- small kernels ----
__global__ void __launch_bounds__(256) dist_kernel(const float* __restrict__ r) {
    int e = blockIdx.x * blockDim.x + threadIdx.x;
    if (e < NEDGES) {
        float x = r[3 * e], y = r[3 * e + 1], z = r[3 * e + 2];
        d_dist[e] = sqrtf(x * x + y * y + z * z);
    }
}

__global__ void __launch_bounds__(256) zero_agg_kernel() {
    int i = blockIdx.x * blockDim.x + threadIdx.x;
    if (i < NATOMS * DDIM) d_agg[i] = 0.0f;
}

__global__ void __launch_bounds__(256) softplus_kernel() {
    int i = blockIdx.x * blockDim.x + threadIdx.x;
    if (i < NATOMS * DDIM) d_h[i] = softplus_f(d_h[i] + d_agg[i]);
}

__global__ void __launch_bounds__(256) zero_pool_kernel() {
    int g = blockIdx.x * blockDim.x + threadIdx.x;
    if (g < NGRAPH) { d_pool[g] = 0.0f; d_cnt[g] = 0; }
}

__global__ void __launch_bounds__(256) pool_kernel(const int* __restrict__ gids,
                                                   const float* __restrict__ out_w) {
    int warp = (blockIdx.x * blockDim.x + threadIdx.x) >> 5;
    int lane = threadIdx.x & 31;
    if (warp >= NATOMS) return;
    float s = 0.0f;
    for (int k = lane; k < DDIM; k += 32)
        s += d_h[(size_t)warp * DDIM + k] * out_w[k];
#pragma unroll
    for (int off = 16; off > 0; off >>= 1)
        s += __shfl_xor_sync(0xFFFFFFFFu, s, off);
    if (lane == 0) {
        atomicAdd(&d_pool[gids[warp]], s);
        atomicAdd(&d_cnt[gids[warp]], 1);
    }
}

__global__ void __launch_bounds__(256) final_kernel(const float* __restrict__ out_b,
                                                    float* __restrict__ out) {
    int g = blockIdx.x * blockDim.x + threadIdx.x;
    if (g < NGRAPH)
        out[g] = d_pool[g] / fmaxf((float)d_cnt[g], 1.0f) + out_b[0];
}

// ---- embedding: h = af_table[atom_types] @ emb_w + emb_b ----
__global__ void __launch_bounds__(256) embed_kernel(const int* __restrict__ atom_types,
                                                    const float* __restrict__ af,
                                                    const float* __restrict__ emb_w,
                                                    const float* __restrict__ emb_b) {
    extern __shared__ float sm[];
    float* xa = sm;  // [ADIM][PADR] k-major
    __shared__ int sT[TE];
    int tid = threadIdx.x, d = tid;
    int row0 = blockIdx.x * TE;
    if (tid < TE) {
        int row = row0 + tid;
        sT[tid] = (row < NATOMS) ? atom_types[row] : 0;
    }
    __syncthreads();
    for (int idx = tid; idx < TE * ADIM; idx += 256) {
        int r = idx / ADIM, k = idx - r * ADIM;
        xa[k * PADR + r] = (row0 + r < NATOMS) ? af[(size_t)sT[r] * ADIM + k] : 0.0f;
    }
    __syncthreads();
    unsigned long long acc[16];
    gemm32(emb_w, xa, ADIM, d, acc);
    float b = emb_b[d];
#pragma unroll
    for (int j = 0; j < 16; j++) {
        float lo, hi; unpack2f(acc[j], lo, hi);
        int r0 = 2 * j, r1 = 2 * j + 1;
        if (row0 + r0 < NATOMS) d_h[(size_t)(row0 + r0) * DDIM + d] = lo + b;
        if (row0 + r1 < NATOMS) d_h[(size_t)(row0 + r1) * DDIM + d] = hi + b;
    }
}

// ---- node kernel: both src/dst 2-layer MLPs from one h tile ----
__global__ void __launch_bounds__(256) node_kernel(
    const float* __restrict__ W1s, const float* __restrict__ b1s,
    const float* __restrict__ W2s, const float* __restrict__ b2s,
    const float* __restrict__ W1d, const float* __restrict__ b1d,
    const float* __restrict__ W2d, const float* __restrict__ b2d) {
    extern __shared__ float sm[];
    float* xa = sm;                 // input tile   [256][PADR]
    float* xb = sm + DDIM * PADR;   // hidden tile  [256][PADR]
    int tid = threadIdx.x, d = tid;
    int row0 = blockIdx.x * TE;
    for (int idx = tid; idx < TE * DDIM; idx += 256) {
        int r = idx >> 8, k = idx & 255;
        int row = row0 + r;
        xa[k * PADR + r] = (row < NATOMS) ? d_h[(size_t)row * DDIM + k] : 0.0f;
    }
    __syncthreads();
    unsigned long long acc[16];

    // src branch
    gemm32(W1s, xa, DDIM, d, acc);
    {
        float b = b1s[d];
#pragma unroll
        for (int j = 0; j < 16; j++) {
            float lo, hi; unpack2f(acc[j], lo, hi);
            xb[d * PADR + 2 * j]     = mish_f(lo + b);
            xb[d * PADR + 2 * j + 1] = mish_f(hi + b);
        }
    }
    __syncthreads();
    gemm32(W2s, xb, DDIM, d, acc);
    {
        float b = b2s[d];
#pragma unroll
        for (int j = 0; j < 16; j++) {
            float lo, hi; unpack2f(acc[j], lo, hi);
            int r0 = 2 * j, r1 = 2 * j + 1;
            if (row0 + r0 < NATOMS) d_hsrc[(size_t)(row0 + r0) * DDIM + d] = lo + b;
            if (row0 + r1 < NATOMS) d_hsrc[(size_t)(row0 + r1) * DDIM + d] = hi + b;
        }
    }
    __syncthreads();

    // dst branch (xa still intact)
    gemm32(W1d, xa, DDIM, d, acc);
    {
        float b = b1d[d];
#pragma unroll
        for (int j = 0; j < 16; j++) {
            float lo, hi; unpack2f(acc[j], lo, hi);
            xb[d * PADR + 2 * j]     = mish_f(lo + b);
            xb[d * PADR + 2 * j + 1] = mish_f(hi + b);
        }
    }
    __syncthreads();
    gemm32(W2d, xb, DDIM, d, acc);
    {
        float b = b2d[d];
#pragma unroll
        for (int j = 0; j < 16; j++) {
            float lo, hi; unpack2f(acc[j], lo, hi);
            int r0 = 2 * j, r1 = 2 * j + 1;
            if (row0 + r0 < NATOMS) d_hdst[(size_t)(row0 + r0) * DDIM + d] = lo + b;
            if (row0 + r1 < NATOMS) d_hdst[(size_t)(row0 + r1) * DDIM + d] = hi + b;
        }
    }
}

// ---- fused edge kernel: RBF -> edge MLP -> Coulomb combine -> m MLP -> atomic agg ----
__global__ void __launch_bounds__(256) edge_kernel(
    const int* __restrict__ esrc, const int* __restrict__ edst,
    const float* __restrict__ W1e, const float* __restrict__ b1e,
    const float* __restrict__ W2e, const float* __restrict__ b2e,
    const float* __restrict__ W1m, const float* __restrict__ b1m,
    const float* __restrict__ W2m, const float* __restrict__ b2m) {
    extern __shared__ float sm[];
    float* xa = sm;
    float* xb = sm + DDIM * PADR;
    __shared__ int   sSrc[TE], sDst[TE];
    __shared__ float sDist[TE];
    int tid = threadIdx.x, d = tid;
    int e0 = blockIdx.x * TE;
    if (tid < TE) {
        sSrc[tid]  = esrc[e0 + tid];
        sDst[tid]  = edst[e0 + tid];
        sDist[tid] = d_dist[e0 + tid];
    }
    __syncthreads();

    // RBF expansion into xa (thread d = RBF bin d, all 32 edges)
    {
        float c = (float)d * (1.0f / 255.0f);
#pragma unroll
        for (int r = 0; r < TE; r++) {
            float t = sDist[r] - c;
            xa[d * PADR + r] = __expf(-255.0f * t * t);
        }
    }
    __syncthreads();

    unsigned long long acc[16];

    // edge MLP layer 1: hid = mish(ef @ W1e + b1e)
    gemm32(W1e, xa, DDIM, d, acc);
    {
        float b = b1e[d];
#pragma unroll
        for (int j = 0; j < 16; j++) {
            float lo, hi; unpack2f(acc[j], lo, hi);
            xb[d * PADR + 2 * j]     = mish_f(lo + b);
            xb[d * PADR + 2 * j + 1] = mish_f(hi + b);
        }
    }
    __syncthreads();

    // edge MLP layer 2 + Coulomb combine: hn = h_src*h_dst*COEF/e_lin
    gemm32(W2e, xb, DDIM, d, acc);
    {
        float b = b2e[d];
#pragma unroll
        for (int j = 0; j < 16; j++) {
            float lo, hi; unpack2f(acc[j], lo, hi);
            int r0 = 2 * j, r1 = 2 * j + 1;
            float hn0 = d_hsrc[(size_t)sSrc[r0] * DDIM + d] *
                        d_hdst[(size_t)sDst[r0] * DDIM + d] * COEF_F;
            float hn1 = d_hsrc[(size_t)sSrc[r1] * DDIM + d] *
                        d_hdst[(size_t)sDst[r1] * DDIM + d] * COEF_F;
            xa[d * PADR + r0] = __fdividef(hn0, lo + b);
            xa[d * PADR + r1] = __fdividef(hn1, hi + b);
        }
    }
    __syncthreads();

    // m MLP layer 1
    gemm32(W1m, xa, DDIM, d, acc);
    {
        float b = b1m[d];
#pragma unroll
        for (int j = 0; j < 16; j++) {
            float lo, hi; unpack2f(acc[j], lo, hi);
            xb[d * PADR + 2 * j]     = mish_f(lo + b);
            xb[d * PADR + 2 * j + 1] = mish_f(hi + b);
        }
    }
    __syncthreads();

    // m MLP layer 2 + segment-sum scatter
    gemm32(W2m, xb, DDIM, d, acc);
    {
        float b = b2m[d];
#pragma unroll
        for (int j = 0; j < 16; j++) {
            float lo, hi; unpack2f(acc[j], lo, hi);
            int r0 = 2 * j, r1 = 2 * j + 1;
            atomicAdd(&d_agg[(size_t)sDst[r0] * DDIM + d], lo + b);
            atomicAdd(&d_agg[(size_t)sDst[r1] * DDIM + d], hi + b);
        }
    }
}

extern "C" void kernel_launch(void* const* d_in, const int* in_sizes, int n_in,
                              void* d_out, int out_size) {
    const int*   atom_types = (const int*)  d_in[0];
    const int*   esrc       = (const int*)  d_in[1];
    const int*   edst       = (const int*)  d_in[2];
    const int*   gids       = (const int*)  d_in[3];
    const float* r          = (const float*)d_in[4];
    const float* af         = (const float*)d_in[5];
    const float* emb_w      = (const float*)d_in[6];
    const float* emb_b      = (const float*)d_in[7];
    const float* cw1        = (const float*)d_in[8];
    const float* cb1        = (const float*)d_in[9];
    const float* cw2        = (const float*)d_in[10];
    const float* cb2        = (const float*)d_in[11];
    const float* out_w      = (const float*)d_in[12];
    const float* out_b      = (const float*)d_in[13];
    float* out = (float*)d_out;

    const int SMEM_BIG   = 2 * DDIM * PADR * 4;   // 73728 B
    const int SMEM_EMBED = ADIM * PADR * 4;
    cudaFuncSetAttribute(edge_kernel,  cudaFuncAttributeMaxDynamicSharedMemorySize, SMEM_BIG);
    cudaFuncSetAttribute(node_kernel,  cudaFuncAttributeMaxDynamicSharedMemorySize, SMEM_BIG);
    cudaFuncSetAttribute(embed_kernel, cudaFuncAttributeMaxDynamicSharedMemorySize, SMEM_EMBED);

    dist_kernel<<<(NEDGES + 255) / 256, 256>>>(r);
    embed_kernel<<<(NATOMS + TE - 1) / TE, 256, SMEM_EMBED>>>(atom_types, af, emb_w, emb_b);

    const size_t MM = (size_t)DDIM * DDIM;
    for (int l = 0; l < LLAYERS; l++) {
        const float* W1 = cw1 + (size_t)l * 4 * MM;
        const float* B1 = cb1 + (size_t)l * 4 * DDIM;
        const float* W2 = cw2 + (size_t)l * 4 * MM;
        const float* B2 = cb2 + (size_t)l * 4 * DDIM;

        node_kernel<<<(NATOMS + TE - 1) / TE, 256, SMEM_BIG>>>(
            W1 + 0 * MM, B1 + 0 * DDIM, W2 + 0 * MM, B2 + 0 * DDIM,
            W1 + 1 * MM, B1 + 1 * DDIM, W2 + 1 * MM, B2 + 1 * DDIM);

        zero_agg_kernel<<<(NATOMS * DDIM + 255) / 256, 256>>>();

        edge_kernel<<<NEDGES / TE, 256, SMEM_BIG>>>(
            esrc, edst,
            W1 + 2 * MM, B1 + 2 * DDIM, W2 + 2 * MM, B2 + 2 * DDIM,
            W1 + 3 * MM, B1 + 3 * DDIM, W2 + 3 * MM, B2 + 3 * DDIM);

        softplus_kernel<<<(NATOMS * DDIM + 255) / 256, 256>>>();
    }

    zero_pool_kernel<<<(NGRAPH + 255) / 256, 256>>>();
    pool_kernel<<<(NATOMS * 32 + 255) / 256, 256>>>(gids, out_w);
    final_kernel<<<(NGRAPH + 255) / 256, 256>>>(out_b, out);
}

// round 4
// speedup vs baseline: 1.0342x; 1.0007x over previous
#include <cuda_runtime.h>
#include <math.h>

#define NATOMS 25000
#define NEDGES 300000
#define NGRAPH 500
#define DDIM   256
#define ADIM   200
#define KEMB   224     // ADIM padded to multiple of 32 (xa rows [200,224) are zero)
#define LLAYERS 3
#define TE     32      // rows (edges/atoms) per block tile
#define PADR   36      // smem row stride (k-major): 144B, 16B-aligned for LDS.128

#define COEF_F ((float)(1.602176634e-19 * 1.602176634e-19 / \
                 (4.0 * 3.14159265358979323846 * 8.8541878128e-12 * 1e-10)))

// ---- scratch (static device globals; no allocation) ----
__device__ float d_dist[NEDGES];
__device__ float d_h   [NATOMS * DDIM];
__device__ float d_hsrc[NATOMS * DDIM];
__device__ float d_hdst[NATOMS * DDIM];
__device__ float d_agg [NATOMS * DDIM];
__device__ float d_pool[NGRAPH];
__device__ int   d_cnt [NGRAPH];

// ---- packed f32x2 helpers ----
__device__ __forceinline__ unsigned long long pack2f(float lo, float hi) {
    unsigned long long v;
    asm("mov.b64 %0, {%1, %2};" : "=l"(v) : "f"(lo), "f"(hi));
    return v;
}
__device__ __forceinline__ void unpack2f(unsigned long long v, float& lo, float& hi) {
    asm("mov.b64 {%0, %1}, %2;" : "=f"(lo), "=f"(hi) : "l"(v));
}
__device__ __forceinline__ void fma2(unsigned long long& a, unsigned long long x, unsigned long long w) {
    asm("fma.rn.f32x2 %0, %1, %2, %0;" : "+l"(a) : "l"(x), "l"(w));
}

__device__ __forceinline__ float softplus_f(float x) {
    return fmaxf(x, 0.0f) + __logf(1.0f + __expf(-fabsf(x)));
}
// mish(x) = x * tanh(softplus(x)) = x * (p^2-1)/(p^2+1), p = 1+e^x
__device__ __forceinline__ float mish_f(float x) {
    float ex = __expf(fminf(x, 20.0f));
    float p  = 1.0f + ex;
    float p2 = p * p;
    return x * __fdividef(p2 - 1.0f, p2 + 1.0f);
}

// ---- pipelined tile GEMM ----
// Plain W row loads (k guaranteed in-bounds by caller).
__device__ __forceinline__ void ldw8(float w[8], const float* __restrict__ W, int k, int d) {
#pragma unroll
    for (int i = 0; i < 8; i++) w[i] = __ldg(W + (size_t)(k + i) * DDIM + d);
}
// Clamped variant for the embed path: rows >= kmax alias row kmax-1 (in-bounds);
// the matching xs rows are zero so the value is multiplied away.
__device__ __forceinline__ void ldw8c(float w[8], const float* __restrict__ W, int k, int d, int kmax) {
#pragma unroll
    for (int i = 0; i < 8; i++) {
        int kk = k + i; if (kk >= kmax) kk = kmax - 1;
        w[i] = __ldg(W + (size_t)kk * DDIM + d);
    }
}

__device__ __forceinline__ void fma8(unsigned long long acc[16], const float w[8],
                                     const float* __restrict__ xs) {
#pragma unroll
    for (int i = 0; i < 8; i++) {
        unsigned long long wv = pack2f(w[i], w[i]);
        const ulonglong2* xr = (const ulonglong2*)(xs + (size_t)i * PADR);
#pragma unroll
        for (int j2 = 0; j2 < 8; j2++) {
            ulonglong2 v = xr[j2];
            fma2(acc[2 * j2],     v.x, wv);
            fma2(acc[2 * j2 + 1], v.y, wv);
        }
    }
}

// out[r][d] = sum_k xs[k*PADR + r] * W[k*256 + d]; K % 32 == 0, all W rows valid.
// W streamed through a 4x8-register ping-pong pipeline: each 8-row W batch is
// issued ~half a k-tile (hundreds of own-warp issue slots) before consumption,
// hiding L2 latency without touching the LDS/FMA inner mix.
__device__ __forceinline__ void gemm32(const float* __restrict__ W,
                                       const float* __restrict__ xs,
                                       int K, int d, unsigned long long acc[16]) {
#pragma unroll
    for (int j = 0; j < 16; j++) acc[j] = 0ULL;
    float wa[8], wb[8], wc[8], wd_[8];
    ldw8(wa, W, 0, d);
    ldw8(wb, W, 8, d);
    for (int k0 = 0; k0 < K; k0 += 32) {
        int kn = (k0 + 32 < K) ? k0 + 32 : 0;
        ldw8(wc,  W, k0 + 16, d);
        ldw8(wd_, W, k0 + 24, d);
        fma8(acc, wa, xs + (size_t)k0 * PADR);
        fma8(acc, wb, xs + (size_t)(k0 + 8) * PADR);
        ldw8(wa, W, kn, d);
        ldw8(wb, W, kn + 8, d);
        fma8(acc, wc,  xs + (size_t)(k0 + 16) * PADR);
        fma8(acc, wd_, xs + (size_t)(k0 + 24) * PADR);
    }
}

// Embed variant: logical K = KEMB (multiple of 32) but W only has kmax=ADIM
// valid rows; row indices are clamped (values beyond kmax multiply zero xs rows).
__device__ __forceinline__ void gemm32_clamp(const float* __restrict__ W,
                                             const float* __restrict__ xs,
                                             int K, int kmax, int d,
                                             unsigned long long acc[16]) {
#pragma unroll
    for (int j = 0; j < 16; j++) acc[j] = 0ULL;
    float wa[8], wb[8], wc[8], wd_[8];
    ldw8c(wa, W, 0, d, kmax);
    ldw8c(wb, W, 8, d, kmax);
    for (int k0 = 0; k0 < K; k0 += 32) {
        int kn = (k0 + 32 < K) ? k0 + 32 : 0;
        ldw8c(wc,  W, k0 + 16, d, kmax);
        ldw8c(wd_, W, k0 + 24, d, kmax);
        fma8(acc, wa, xs + (size_t)k0 * PADR);
        fma8(acc, wb, xs + (size_t)(k0 + 8) * PADR);
        ldw8c(wa, W, kn, d, kmax);
        ldw8c(wb, W, kn + 8, d, kmax);
        fma8(acc, wc,  xs + (size_t)(k0 + 16) * PADR);
        fma8(acc, wd_, xs + (size_t)(k0 + 24) * PADR);
    }
}

// ---- small kernels ----
__global__ void __launch_bounds__(256) dist_kernel(const float* __restrict__ r) {
    int e = blockIdx.x * blockDim.x + threadIdx.x;
    if (e < NEDGES) {
        float x = r[3 * e], y = r[3 * e + 1], z = r[3 * e + 2];
        d_dist[e] = sqrtf(x * x + y * y + z * z);
    }
}

__global__ void __launch_bounds__(256) zero_pool_kernel() {
    int g = blockIdx.x * blockDim.x + threadIdx.x;
    if (g < NGRAPH) { d_pool[g] = 0.0f; d_cnt[g] = 0; }
}

// pool applies the final softplus(h + agg) itself (layer-3 epilogue fused here)
__global__ void __launch_bounds__(256) pool_kernel(const int* __restrict__ gids,
                                                   const float* __restrict__ out_w) {
    int warp = (blockIdx.x * blockDim.x + threadIdx.x) >> 5;
    int lane = threadIdx.x & 31;
    if (warp >= NATOMS) return;
    float s = 0.0f;
    for (int k = lane; k < DDIM; k += 32) {
        size_t off = (size_t)warp * DDIM + k;
        s += softplus_f(d_h[off] + d_agg[off]) * out_w[k];
    }
#pragma unroll
    for (int off = 16; off > 0; off >>= 1)
        s += __shfl_xor_sync(0xFFFFFFFFu, s, off);
    if (lane == 0) {
        atomicAdd(&d_pool[gids[warp]], s);
        atomicAdd(&d_cnt[gids[warp]], 1);
    }
}

__global__ void __launch_bounds__(256) final_kernel(const float* __restrict__ out_b,
                                                    float* __restrict__ out) {
    int g = blockIdx.x * blockDim.x + threadIdx.x;
    if (g < NGRAPH)
        out[g] = d_pool[g] / fmaxf((float)d_cnt[g], 1.0f) + out_b[0];
}

// ---- embedding: h = af_table[atom_types] @ emb_w + emb_b ----
__global__ void __launch_bounds__(256) embed_kernel(const int* __restrict__ atom_types,
                                                    const float* __restrict__ af,
                                                    const float* __restrict__ emb_w,
                                                    const float* __restrict__ emb_b) {
    extern __shared__ float sm[];
    float* xa = sm;  // [KEMB][PADR] k-major (rows >= ADIM zero)
    __shared__ int sT[TE];
    int tid = threadIdx.x, d = tid;
    int row0 = blockIdx.x * TE;
    if (tid < TE) {
        int row = row0 + tid;
        sT[tid] = (row < NATOMS) ? atom_types[row] : 0;
    }
    __syncthreads();
    for (int idx = tid; idx < TE * KEMB; idx += 256) {
        int r = idx / KEMB, k = idx - r * KEMB;
        float v = 0.0f;
        if (k < ADIM && row0 + r < NATOMS) v = af[(size_t)sT[r] * ADIM + k];
        xa[k * PADR + r] = v;
    }
    __syncthreads();
    unsigned long long acc[16];
    gemm32_clamp(emb_w, xa, KEMB, ADIM, d, acc);  // W rows clamped in-bounds
    float b = emb_b[d];
#pragma unroll
    for (int j = 0; j < 16; j++) {
        float lo, hi; unpack2f(acc[j], lo, hi);
        int r0 = 2 * j, r1 = 2 * j + 1;
        if (row0 + r0 < NATOMS) d_h[(size_t)(row0 + r0) * DDIM + d] = lo + b;
        if (row0 + r1 < NATOMS) d_h[(size_t)(row0 + r1) * DDIM + d] = hi + b;
    }
}

// ---- node kernel: softplus(h+agg) update, zero agg, then src/dst MLPs ----
__global__ void __launch_bounds__(256) node_kernel(
    int use_agg,
    const float* __restrict__ W1s, const float* __restrict__ b1s,
    const float* __restrict__ W2s, const float* __restrict__ b2s,
    const float* __restrict__ W1d, const float* __restrict__ b1d,
    const float* __restrict__ W2d, const float* __restrict__ b2d) {
    extern __shared__ float sm[];
    float* xa = sm;                 // input tile   [256][PADR]
    float* xb = sm + DDIM * PADR;   // hidden tile  [256][PADR]
    int tid = threadIdx.x, d = tid;
    int row0 = blockIdx.x * TE;
    for (int idx = tid; idx < TE * DDIM; idx += 256) {
        int r = idx >> 8, k = idx & 255;
        int row = row0 + r;
        float v = 0.0f;
        if (row < NATOMS) {
            size_t off = (size_t)row * DDIM + k;
            if (use_agg) {
                v = softplus_f(d_h[off] + d_agg[off]);
                d_h[off] = v;          // persist updated h for next layer / pool
            } else {
                v = d_h[off];
            }
            d_agg[off] = 0.0f;         // ready for this layer's edge atomics
        }
        xa[k * PADR + r] = v;
    }
    __syncthreads();
    unsigned long long acc[16];

    // src branch
    gemm32(W1s, xa, DDIM, d, acc);
    {
        float b = b1s[d];
#pragma unroll
        for (int j = 0; j < 16; j++) {
            float lo, hi; unpack2f(acc[j], lo, hi);
            xb[d * PADR + 2 * j]     = mish_f(lo + b);
            xb[d * PADR + 2 * j + 1] = mish_f(hi + b);
        }
    }
    __syncthreads();
    gemm32(W2s, xb, DDIM, d, acc);
    {
        float b = b2s[d];
#pragma unroll
        for (int j = 0; j < 16; j++) {
            float lo, hi; unpack2f(acc[j], lo, hi);
            int r0 = 2 * j, r1 = 2 * j + 1;
            if (row0 + r0 < NATOMS) d_hsrc[(size_t)(row0 + r0) * DDIM + d] = lo + b;
            if (row0 + r1 < NATOMS) d_hsrc[(size_t)(row0 + r1) * DDIM + d] = hi + b;
        }
    }
    __syncthreads();

    // dst branch (xa still intact)
    gemm32(W1d, xa, DDIM, d, acc);
    {
        float b = b1d[d];
#pragma unroll
        for (int j = 0; j < 16; j++) {
            float lo, hi; unpack2f(acc[j], lo, hi);
            xb[d * PADR + 2 * j]     = mish_f(lo + b);
            xb[d * PADR + 2 * j + 1] = mish_f(hi + b);
        }
    }
    __syncthreads();
    gemm32(W2d, xb, DDIM, d, acc);
    {
        float b = b2d[d];
#pragma unroll
        for (int j = 0; j < 16; j++) {
            float lo, hi; unpack2f(acc[j], lo, hi);
            int r0 = 2 * j, r1 = 2 * j + 1;
            if (row0 + r0 < NATOMS) d_hdst[(size_t)(row0 + r0) * DDIM + d] = lo + b;
            if (row0 + r1 < NATOMS) d_hdst[(size_t)(row0 + r1) * DDIM + d] = hi + b;
        }
    }
}

// ---- fused edge kernel: RBF -> edge MLP -> Coulomb combine -> m MLP -> atomic agg ----
__global__ void __launch_bounds__(256) edge_kernel(
    const int* __restrict__ esrc, const int* __restrict__ edst,
    const float* __restrict__ W1e, const float* __restrict__ b1e,
    const float* __restrict__ W2e, const float* __restrict__ b2e,
    const float* __restrict__ W1m, const float* __restrict__ b1m,
    const float* __restrict__ W2m, const float* __restrict__ b2m) {
    extern __shared__ float sm[];
    float* xa = sm;
    float* xb = sm + DDIM * PADR;
    __shared__ int   sSrc[TE], sDst[TE];
    __shared__ float sDist[TE];
    int tid = threadIdx.x, d = tid;
    int e0 = blockIdx.x * TE;
    if (tid < TE) {
        sSrc[tid]  = esrc[e0 + tid];
        sDst[tid]  = edst[e0 + tid];
        sDist[tid] = d_dist[e0 + tid];
    }
    __syncthreads();

    // RBF expansion into xa (thread d = RBF bin d, all 32 edges)
    {
        float c = (float)d * (1.0f / 255.0f);
#pragma unroll
        for (int r = 0; r < TE; r++) {
            float t = sDist[r] - c;
            xa[d * PADR + r] = __expf(-255.0f * t * t);
        }
    }
    __syncthreads();

    unsigned long long acc[16];

    gemm32(W1e, xa, DDIM, d, acc);
    {
        float b = b1e[d];
#pragma unroll
        for (int j = 0; j < 16; j++) {
            float lo, hi; unpack2f(acc[j], lo, hi);
            xb[d * PADR + 2 * j]     = mish_f(lo + b);
            xb[d * PADR + 2 * j + 1] = mish_f(hi + b);
        }
    }
    __syncthreads();

    gemm32(W2e, xb, DDIM, d, acc);
    {
        float b = b2e[d];
#pragma unroll
        for (int j = 0; j < 16; j++) {
            float lo, hi; unpack2f(acc[j], lo, hi);
            int r0 = 2 * j, r1 = 2 * j + 1;
            float hn0 = d_hsrc[(size_t)sSrc[r0] * DDIM + d] *
                        d_hdst[(size_t)sDst[r0] * DDIM + d] * COEF_F;
            float hn1 = d_hsrc[(size_t)sSrc[r1] * DDIM + d] *
                        d_hdst[(size_t)sDst[r1] * DDIM + d] * COEF_F;
            xa[d * PADR + r0] = __fdividef(hn0, lo + b);
            xa[d * PADR + r1] = __fdividef(hn1, hi + b);
        }
    }
    __syncthreads();

    gemm32(W1m, xa, DDIM, d, acc);
    {
        float b = b1m[d];
#pragma unroll
        for (int j = 0; j < 16; j++) {
            float lo, hi; unpack2f(acc[j], lo, hi);
            xb[d * PADR + 2 * j]     = mish_f(lo + b);
            xb[d * PADR + 2 * j + 1] = mish_f(hi + b);
        }
    }
    __syncthreads();

    gemm32(W2m, xb, DDIM, d, acc);
    {
        float b = b2m[d];
#pragma unroll
        for (int j = 0; j < 16; j++) {
            float lo, hi; unpack2f(acc[j], lo, hi);
            int r0 = 2 * j, r1 = 2 * j + 1;
            atomicAdd(&d_agg[(size_t)sDst[r0] * DDIM + d], lo + b);
            atomicAdd(&d_agg[(size_t)sDst[r1] * DDIM + d], hi + b);
        }
    }
}

extern "C" void kernel_launch(void* const* d_in, const int* in_sizes, int n_in,
                              void* d_out, int out_size) {
    const int*   atom_types = (const int*)  d_in[0];
    const int*   esrc       = (const int*)  d_in[1];
    const int*   edst       = (const int*)  d_in[2];
    const int*   gids       = (const int*)  d_in[3];
    const float* r          = (const float*)d_in[4];
    const float* af         = (const float*)d_in[5];
    const float* emb_w      = (const float*)d_in[6];
    const float* emb_b      = (const float*)d_in[7];
    const float* cw1        = (const float*)d_in[8];
    const float* cb1        = (const float*)d_in[9];
    const float* cw2        = (const float*)d_in[10];
    const float* cb2        = (const float*)d_in[11];
    const float* out_w      = (const float*)d_in[12];
    const float* out_b      = (const float*)d_in[13];
    float* out = (float*)d_out;

    const int SMEM_BIG   = 2 * DDIM * PADR * 4;   // 73728 B
    const int SMEM_EMBED = KEMB * PADR * 4;
    cudaFuncSetAttribute(edge_kernel,  cudaFuncAttributeMaxDynamicSharedMemorySize, SMEM_BIG);
    cudaFuncSetAttribute(node_kernel,  cudaFuncAttributeMaxDynamicSharedMemorySize, SMEM_BIG);
    cudaFuncSetAttribute(embed_kernel, cudaFuncAttributeMaxDynamicSharedMemorySize, SMEM_EMBED);

    dist_kernel<<<(NEDGES + 255) / 256, 256>>>(r);
    embed_kernel<<<(NATOMS + TE - 1) / TE, 256, SMEM_EMBED>>>(atom_types, af, emb_w, emb_b);

    const size_t MM = (size_t)DDIM * DDIM;
    for (int l = 0; l < LLAYERS; l++) {
        const float* W1 = cw1 + (size_t)l * 4 * MM;
        const float* B1 = cb1 + (size_t)l * 4 * DDIM;
        const float* W2 = cw2 + (size_t)l * 4 * MM;
        const float* B2 = cb2 + (size_t)l * 4 * DDIM;

        node_kernel<<<(NATOMS + TE - 1) / TE, 256, SMEM_BIG>>>(
            l > 0 ? 1 : 0,
            W1 + 0 * MM, B1 + 0 * DDIM, W2 + 0 * MM, B2 + 0 * DDIM,
            W1 + 1 * MM, B1 + 1 * DDIM, W2 + 1 * MM, B2 + 1 * DDIM);

        edge_kernel<<<NEDGES / TE, 256, SMEM_BIG>>>(
            esrc, edst,
            W1 + 2 * MM, B1 + 2 * DDIM, W2 + 2 * MM, B2 + 2 * DDIM,
            W1 + 3 * MM, B1 + 3 * DDIM, W2 + 3 * MM, B2 + 3 * DDIM);
    }

    zero_pool_kernel<<<(NGRAPH + 255) / 256, 256>>>();
    pool_kernel<<<(NATOMS * 32 + 255) / 256, 256>>>(gids, out_w);
    final_kernel<<<(NGRAPH + 255) / 256, 256>>>(out_b, out);
}

// round 5
// speedup vs baseline: 1.4922x; 1.4428x over previous
#include <cuda_runtime.h>
#include <math.h>

#define NATOMS 25000
#define NEDGES 300000
#define NGRAPH 500
#define DDIM   256
#define ADIM   200
#define KEMB   224     // ADIM padded to multiple of 16 (xa rows [200,224) are zero)
#define LLAYERS 3
#define TE     32      // rows (edges/atoms) per block tile
#define PADR   36      // smem row stride (k-major): 144B; 16-float group => 64B aligned

#define COEF_F ((float)(1.602176634e-19 * 1.602176634e-19 / \
                 (4.0 * 3.14159265358979323846 * 8.8541878128e-12 * 1e-10)))

// ---- scratch (static device globals; no allocation) ----
__device__ float d_dist[NEDGES];
__device__ float d_h   [NATOMS * DDIM];
__device__ float d_hsrc[NATOMS * DDIM];
__device__ float d_hdst[NATOMS * DDIM];
__device__ float d_agg [NATOMS * DDIM];
__device__ float d_pool[NGRAPH];
__device__ int   d_cnt [NGRAPH];

// ---- packed f32x2 helpers ----
__device__ __forceinline__ unsigned long long pack2f(float lo, float hi) {
    unsigned long long v;
    asm("mov.b64 %0, {%1, %2};" : "=l"(v) : "f"(lo), "f"(hi));
    return v;
}
__device__ __forceinline__ void unpack2f(unsigned long long v, float& lo, float& hi) {
    asm("mov.b64 {%0, %1}, %2;" : "=f"(lo), "=f"(hi) : "l"(v));
}
__device__ __forceinline__ void fma2(unsigned long long& a, unsigned long long x, unsigned long long w) {
    asm("fma.rn.f32x2 %0, %1, %2, %0;" : "+l"(a) : "l"(x), "l"(w));
}

__device__ __forceinline__ float softplus_f(float x) {
    return fmaxf(x, 0.0f) + __logf(1.0f + __expf(-fabsf(x)));
}
// mish(x) = x * tanh(softplus(x)) = x * (p^2-1)/(p^2+1), p = 1+e^x
__device__ __forceinline__ float mish_f(float x) {
    float ex = __expf(fminf(x, 20.0f));
    float p  = 1.0f + ex;
    float p2 = p * p;
    return x * __fdividef(p2 - 1.0f, p2 + 1.0f);
}

// ==== register-blocked tile GEMM: per thread 2 cols x 16 rows ====
// Thread map: c = tid & 127 -> cols {c, c+128}; rg = tid >> 7 -> rows [rg*16, rg*16+16).
// acc[j]   (j=0..7): col c,     rows (2j, 2j+1) of the group
// acc[8+j] (j=0..7): col c+128, rows (2j, 2j+1)
// Per k: 4x LDS.128 (broadcast) + 2x LDG(W) for 16 FFMA2  (wf/FFMA2 = 0.375).

__device__ __forceinline__ void ldw4x2(float w[4][2], const float* __restrict__ W,
                                       int k, int c) {
#pragma unroll
    for (int i = 0; i < 4; i++) {
        w[i][0] = __ldg(W + (size_t)(k + i) * DDIM + c);
        w[i][1] = __ldg(W + (size_t)(k + i) * DDIM + c + 128);
    }
}
// Clamped variant (embed): rows >= kmax alias row kmax-1 (in-bounds; matching xs rows are zero)
__device__ __forceinline__ void ldw4x2c(float w[4][2], const float* __restrict__ W,
                                        int k, int c, int kmax) {
#pragma unroll
    for (int i = 0; i < 4; i++) {
        int kk = k + i; if (kk >= kmax) kk = kmax - 1;
        w[i][0] = __ldg(W + (size_t)kk * DDIM + c);
        w[i][1] = __ldg(W + (size_t)kk * DDIM + c + 128);
    }
}

__device__ __forceinline__ void fma4x2(unsigned long long acc[16], const float w[4][2],
                                       const float* __restrict__ xs) {
#pragma unroll
    for (int i = 0; i < 4; i++) {
        unsigned long long wv0 = pack2f(w[i][0], w[i][0]);
        unsigned long long wv1 = pack2f(w[i][1], w[i][1]);
        const ulonglong2* xr = (const ulonglong2*)(xs + (size_t)i * PADR);
#pragma unroll
        for (int j2 = 0; j2 < 4; j2++) {
            ulonglong2 v = xr[j2];
            fma2(acc[2 * j2],         v.x, wv0);
            fma2(acc[2 * j2 + 1],     v.y, wv0);
            fma2(acc[8 + 2 * j2],     v.x, wv1);
            fma2(acc[8 + 2 * j2 + 1], v.y, wv1);
        }
    }
}

// xs must point at the thread's row group base (xa + rg*16). K % 16 == 0.
__device__ __forceinline__ void gemm2x16(const float* __restrict__ W,
                                         const float* __restrict__ xs,
                                         int K, int c, unsigned long long acc[16]) {
#pragma unroll
    for (int j = 0; j < 16; j++) acc[j] = 0ULL;
    float wa[4][2], wb[4][2], wc_[4][2], wd_[4][2];
    ldw4x2(wa, W, 0, c);
    ldw4x2(wb, W, 4, c);
    for (int k0 = 0; k0 < K; k0 += 16) {
        int kn = (k0 + 16 < K) ? k0 + 16 : 0;
        ldw4x2(wc_, W, k0 + 8, c);
        ldw4x2(wd_, W, k0 + 12, c);
        fma4x2(acc, wa, xs + (size_t)k0 * PADR);
        fma4x2(acc, wb, xs + (size_t)(k0 + 4) * PADR);
        ldw4x2(wa, W, kn, c);
        ldw4x2(wb, W, kn + 4, c);
        fma4x2(acc, wc_, xs + (size_t)(k0 + 8) * PADR);
        fma4x2(acc, wd_, xs + (size_t)(k0 + 12) * PADR);
    }
}

__device__ __forceinline__ void gemm2x16_clamp(const float* __restrict__ W,
                                               const float* __restrict__ xs,
                                               int K, int kmax, int c,
                                               unsigned long long acc[16]) {
#pragma unroll
    for (int j = 0; j < 16; j++) acc[j] = 0ULL;
    float wa[4][2], wb[4][2], wc_[4][2], wd_[4][2];
    ldw4x2c(wa, W, 0, c, kmax);
    ldw4x2c(wb, W, 4, c, kmax);
    for (int k0 = 0; k0 < K; k0 += 16) {
        int kn = (k0 + 16 < K) ? k0 + 16 : 0;
        ldw4x2c(wc_, W, k0 + 8, c, kmax);
        ldw4x2c(wd_, W, k0 + 12, c, kmax);
        fma4x2(acc, wa, xs + (size_t)k0 * PADR);
        fma4x2(acc, wb, xs + (size_t)(k0 + 4) * PADR);
        ldw4x2c(wa, W, kn, c, kmax);
        ldw4x2c(wb, W, kn + 4, c, kmax);
        fma4x2(acc, wc_, xs + (size_t)(k0 + 8) * PADR);
        fma4x2(acc, wd_, xs + (size_t)(k0 + 12) * PADR);
    }
}

// Epilogue helper: apply bias+mish and store to k-major smem tile
__device__ __forceinline__ void epi_mish_sts(float* __restrict__ xb,
                                             const unsigned long long acc[16],
                                             float b0, float b1v, int c, int rbase) {
#pragma unroll
    for (int j = 0; j < 8; j++) {
        float lo, hi;
        int r0 = rbase + 2 * j, r1 = r0 + 1;
        unpack2f(acc[j], lo, hi);
        xb[c * PADR + r0] = mish_f(lo + b0);
        xb[c * PADR + r1] = mish_f(hi + b0);
        unpack2f(acc[8 + j], lo, hi);
        xb[(c + 128) * PADR + r0] = mish_f(lo + b1v);
        xb[(c + 128) * PADR + r1] = mish_f(hi + b1v);
    }
}

// ---- small kernels ----
__global__ void __launch_bounds__(256) dist_kernel(const float* __restrict__ r) {
    int e = blockIdx.x * blockDim.x + threadIdx.x;
    if (e < NEDGES) {
        float x = r[3 * e], y = r[3 * e + 1], z = r[3 * e + 2];
        d_dist[e] = sqrtf(x * x + y * y + z * z);
    }
}

__global__ void __launch_bounds__(256) zero_pool_kernel() {
    int g = blockIdx.x * blockDim.x + threadIdx.x;
    if (g < NGRAPH) { d_pool[g] = 0.0f; d_cnt[g] = 0; }
}

// pool applies the final softplus(h + agg) itself (layer-3 epilogue fused here)
__global__ void __launch_bounds__(256) pool_kernel(const int* __restrict__ gids,
                                                   const float* __restrict__ out_w) {
    int warp = (blockIdx.x * blockDim.x + threadIdx.x) >> 5;
    int lane = threadIdx.x & 31;
    if (warp >= NATOMS) return;
    float s = 0.0f;
    for (int k = lane; k < DDIM; k += 32) {
        size_t off = (size_t)warp * DDIM + k;
        s += softplus_f(d_h[off] + d_agg[off]) * out_w[k];
    }
#pragma unroll
    for (int off = 16; off > 0; off >>= 1)
        s += __shfl_xor_sync(0xFFFFFFFFu, s, off);
    if (lane == 0) {
        atomicAdd(&d_pool[gids[warp]], s);
        atomicAdd(&d_cnt[gids[warp]], 1);
    }
}

__global__ void __launch_bounds__(256) final_kernel(const float* __restrict__ out_b,
                                                    float* __restrict__ out) {
    int g = blockIdx.x * blockDim.x + threadIdx.x;
    if (g < NGRAPH)
        out[g] = d_pool[g] / fmaxf((float)d_cnt[g], 1.0f) + out_b[0];
}

// ---- embedding: h = af_table[atom_types] @ emb_w + emb_b ----
__global__ void __launch_bounds__(256) embed_kernel(const int* __restrict__ atom_types,
                                                    const float* __restrict__ af,
                                                    const float* __restrict__ emb_w,
                                                    const float* __restrict__ emb_b) {
    extern __shared__ float sm[];
    float* xa = sm;  // [KEMB][PADR] k-major (rows >= ADIM zero)
    __shared__ int sT[TE];
    int tid = threadIdx.x;
    int c = tid & 127, rg = tid >> 7, rbase = rg * 16;
    int row0 = blockIdx.x * TE;
    if (tid < TE) {
        int row = row0 + tid;
        sT[tid] = (row < NATOMS) ? atom_types[row] : 0;
    }
    __syncthreads();
    for (int idx = tid; idx < TE * KEMB; idx += 256) {
        int r = idx / KEMB, k = idx - r * KEMB;
        float v = 0.0f;
        if (k < ADIM && row0 + r < NATOMS) v = af[(size_t)sT[r] * ADIM + k];
        xa[k * PADR + r] = v;
    }
    __syncthreads();
    unsigned long long acc[16];
    gemm2x16_clamp(emb_w, xa + rbase, KEMB, ADIM, c, acc);
    float b0 = emb_b[c], b1v = emb_b[c + 128];
#pragma unroll
    for (int j = 0; j < 8; j++) {
        float lo, hi;
        int r0 = rbase + 2 * j, r1 = r0 + 1;
        unpack2f(acc[j], lo, hi);
        if (row0 + r0 < NATOMS) d_h[(size_t)(row0 + r0) * DDIM + c] = lo + b0;
        if (row0 + r1 < NATOMS) d_h[(size_t)(row0 + r1) * DDIM + c] = hi + b0;
        unpack2f(acc[8 + j], lo, hi);
        if (row0 + r0 < NATOMS) d_h[(size_t)(row0 + r0) * DDIM + c + 128] = lo + b1v;
        if (row0 + r1 < NATOMS) d_h[(size_t)(row0 + r1) * DDIM + c + 128] = hi + b1v;
    }
}

// ---- node kernel: softplus(h+agg) update, zero agg, then src/dst MLPs ----
__global__ void __launch_bounds__(256) node_kernel(
    int use_agg,
    const float* __restrict__ W1s, const float* __restrict__ b1s,
    const float* __restrict__ W2s, const float* __restrict__ b2s,
    const float* __restrict__ W1d, const float* __restrict__ b1d,
    const float* __restrict__ W2d, const float* __restrict__ b2d) {
    extern __shared__ float sm[];
    float* xa = sm;                 // input tile   [256][PADR]
    float* xb = sm + DDIM * PADR;   // hidden tile  [256][PADR]
    int tid = threadIdx.x;
    int c = tid & 127, rg = tid >> 7, rbase = rg * 16;
    int row0 = blockIdx.x * TE;
    for (int idx = tid; idx < TE * DDIM; idx += 256) {
        int r = idx >> 8, k = idx & 255;
        int row = row0 + r;
        float v = 0.0f;
        if (row < NATOMS) {
            size_t off = (size_t)row * DDIM + k;
            if (use_agg) {
                v = softplus_f(d_h[off] + d_agg[off]);
                d_h[off] = v;          // persist updated h for next layer / pool
            } else {
                v = d_h[off];
            }
            d_agg[off] = 0.0f;         // ready for this layer's edge atomics
        }
        xa[k * PADR + r] = v;
    }
    __syncthreads();
    unsigned long long acc[16];

    // src branch
    gemm2x16(W1s, xa + rbase, DDIM, c, acc);
    epi_mish_sts(xb, acc, b1s[c], b1s[c + 128], c, rbase);
    __syncthreads();
    gemm2x16(W2s, xb + rbase, DDIM, c, acc);
    {
        float b0 = b2s[c], b1v = b2s[c + 128];
#pragma unroll
        for (int j = 0; j < 8; j++) {
            float lo, hi;
            int r0 = rbase + 2 * j, r1 = r0 + 1;
            unpack2f(acc[j], lo, hi);
            if (row0 + r0 < NATOMS) d_hsrc[(size_t)(row0 + r0) * DDIM + c] = lo + b0;
            if (row0 + r1 < NATOMS) d_hsrc[(size_t)(row0 + r1) * DDIM + c] = hi + b0;
            unpack2f(acc[8 + j], lo, hi);
            if (row0 + r0 < NATOMS) d_hsrc[(size_t)(row0 + r0) * DDIM + c + 128] = lo + b1v;
            if (row0 + r1 < NATOMS) d_hsrc[(size_t)(row0 + r1) * DDIM + c + 128] = hi + b1v;
        }
    }
    __syncthreads();

    // dst branch (xa still intact)
    gemm2x16(W1d, xa + rbase, DDIM, c, acc);
    epi_mish_sts(xb, acc, b1d[c], b1d[c + 128], c, rbase);
    __syncthreads();
    gemm2x16(W2d, xb + rbase, DDIM, c, acc);
    {
        float b0 = b2d[c], b1v = b2d[c + 128];
#pragma unroll
        for (int j = 0; j < 8; j++) {
            float lo, hi;
            int r0 = rbase + 2 * j, r1 = r0 + 1;
            unpack2f(acc[j], lo, hi);
            if (row0 + r0 < NATOMS) d_hdst[(size_t)(row0 + r0) * DDIM + c] = lo + b0;
            if (row0 + r1 < NATOMS) d_hdst[(size_t)(row0 + r1) * DDIM + c] = hi + b0;
            unpack2f(acc[8 + j], lo, hi);
            if (row0 + r0 < NATOMS) d_hdst[(size_t)(row0 + r0) * DDIM + c + 128] = lo + b1v;
            if (row0 + r1 < NATOMS) d_hdst[(size_t)(row0 + r1) * DDIM + c + 128] = hi + b1v;
        }
    }
}

// ---- fused edge kernel: RBF -> edge MLP -> Coulomb combine -> m MLP -> atomic agg ----
__global__ void __launch_bounds__(256) edge_kernel(
    const int* __restrict__ esrc, const int* __restrict__ edst,
    const float* __restrict__ W1e, const float* __restrict__ b1e,
    const float* __restrict__ W2e, const float* __restrict__ b2e,
    const float* __restrict__ W1m, const float* __restrict__ b1m,
    const float* __restrict__ W2m, const float* __restrict__ b2m) {
    extern __shared__ float sm[];
    float* xa = sm;
    float* xb = sm + DDIM * PADR;
    __shared__ int   sSrc[TE], sDst[TE];
    __shared__ float sDist[TE];
    int tid = threadIdx.x;
    int c = tid & 127, rg = tid >> 7, rbase = rg * 16;
    int e0 = blockIdx.x * TE;
    if (tid < TE) {
        sSrc[tid]  = esrc[e0 + tid];
        sDst[tid]  = edst[e0 + tid];
        sDist[tid] = d_dist[e0 + tid];
    }
    __syncthreads();

    // RBF expansion into xa: thread tid fills column tid for all 32 rows
    {
        float cc = (float)tid * (1.0f / 255.0f);
#pragma unroll
        for (int r = 0; r < TE; r++) {
            float t = sDist[r] - cc;
            xa[tid * PADR + r] = __expf(-255.0f * t * t);
        }
    }
    __syncthreads();

    unsigned long long acc[16];

    gemm2x16(W1e, xa + rbase, DDIM, c, acc);
    epi_mish_sts(xb, acc, b1e[c], b1e[c + 128], c, rbase);
    __syncthreads();

    gemm2x16(W2e, xb + rbase, DDIM, c, acc);
    {
        float b0 = b2e[c], b1v = b2e[c + 128];
#pragma unroll
        for (int j = 0; j < 8; j++) {
            float lo, hi;
            int r0 = rbase + 2 * j, r1 = r0 + 1;
            int s0 = sSrc[r0], s1 = sSrc[r1], t0 = sDst[r0], t1 = sDst[r1];
            unpack2f(acc[j], lo, hi);
            xa[c * PADR + r0] = __fdividef(
                d_hsrc[(size_t)s0 * DDIM + c] * d_hdst[(size_t)t0 * DDIM + c] * COEF_F, lo + b0);
            xa[c * PADR + r1] = __fdividef(
                d_hsrc[(size_t)s1 * DDIM + c] * d_hdst[(size_t)t1 * DDIM + c] * COEF_F, hi + b0);
            unpack2f(acc[8 + j], lo, hi);
            xa[(c + 128) * PADR + r0] = __fdividef(
                d_hsrc[(size_t)s0 * DDIM + c + 128] * d_hdst[(size_t)t0 * DDIM + c + 128] * COEF_F, lo + b1v);
            xa[(c + 128) * PADR + r1] = __fdividef(
                d_hsrc[(size_t)s1 * DDIM + c + 128] * d_hdst[(size_t)t1 * DDIM + c + 128] * COEF_F, hi + b1v);
        }
    }
    __syncthreads();

    gemm2x16(W1m, xa + rbase, DDIM, c, acc);
    epi_mish_sts(xb, acc, b1m[c], b1m[c + 128], c, rbase);
    __syncthreads();

    gemm2x16(W2m, xb + rbase, DDIM, c, acc);
    {
        float b0 = b2m[c], b1v = b2m[c + 128];
#pragma unroll
        for (int j = 0; j < 8; j++) {
            float lo, hi;
            int r0 = rbase + 2 * j, r1 = r0 + 1;
            int t0 = sDst[r0], t1 = sDst[r1];
            unpack2f(acc[j], lo, hi);
            atomicAdd(&d_agg[(size_t)t0 * DDIM + c], lo + b0);
            atomicAdd(&d_agg[(size_t)t1 * DDIM + c], hi + b0);
            unpack2f(acc[8 + j], lo, hi);
            atomicAdd(&d_agg[(size_t)t0 * DDIM + c + 128], lo + b1v);
            atomicAdd(&d_agg[(size_t)t1 * DDIM + c + 128], hi + b1v);
        }
    }
}

extern "C" void kernel_launch(void* const* d_in, const int* in_sizes, int n_in,
                              void* d_out, int out_size) {
    const int*   atom_types = (const int*)  d_in[0];
    const int*   esrc       = (const int*)  d_in[1];
    const int*   edst       = (const int*)  d_in[2];
    const int*   gids       = (const int*)  d_in[3];
    const float* r          = (const float*)d_in[4];
    const float* af         = (const float*)d_in[5];
    const float* emb_w      = (const float*)d_in[6];
    const float* emb_b      = (const float*)d_in[7];
    const float* cw1        = (const float*)d_in[8];
    const float* cb1        = (const float*)d_in[9];
    const float* cw2        = (const float*)d_in[10];
    const float* cb2        = (const float*)d_in[11];
    const float* out_w      = (const float*)d_in[12];
    const float* out_b      = (const float*)d_in[13];
    float* out = (float*)d_out;

    const int SMEM_BIG   = 2 * DDIM * PADR * 4;   // 73728 B
    const int SMEM_EMBED = KEMB * PADR * 4;
    cudaFuncSetAttribute(edge_kernel,  cudaFuncAttributeMaxDynamicSharedMemorySize, SMEM_BIG);
    cudaFuncSetAttribute(node_kernel,  cudaFuncAttributeMaxDynamicSharedMemorySize, SMEM_BIG);
    cudaFuncSetAttribute(embed_kernel, cudaFuncAttributeMaxDynamicSharedMemorySize, SMEM_EMBED);

    dist_kernel<<<(NEDGES + 255) / 256, 256>>>(r);
    embed_kernel<<<(NATOMS + TE - 1) / TE, 256, SMEM_EMBED>>>(atom_types, af, emb_w, emb_b);

    const size_t MM = (size_t)DDIM * DDIM;
    for (int l = 0; l < LLAYERS; l++) {
        const float* W1 = cw1 + (size_t)l * 4 * MM;
        const float* B1 = cb1 + (size_t)l * 4 * DDIM;
        const float* W2 = cw2 + (size_t)l * 4 * MM;
        const float* B2 = cb2 + (size_t)l * 4 * DDIM;

        node_kernel<<<(NATOMS + TE - 1) / TE, 256, SMEM_BIG>>>(
            l > 0 ? 1 : 0,
            W1 + 0 * MM, B1 + 0 * DDIM, W2 + 0 * MM, B2 + 0 * DDIM,
            W1 + 1 * MM, B1 + 1 * DDIM, W2 + 1 * MM, B2 + 1 * DDIM);

        edge_kernel<<<NEDGES / TE, 256, SMEM_BIG>>>(
            esrc, edst,
            W1 + 2 * MM, B1 + 2 * DDIM, W2 + 2 * MM, B2 + 2 * DDIM,
            W1 + 3 * MM, B1 + 3 * DDIM, W2 + 3 * MM, B2 + 3 * DDIM);
    }

    zero_pool_kernel<<<(NGRAPH + 255) / 256, 256>>>();
    pool_kernel<<<(NATOMS * 32 + 255) / 256, 256>>>(gids, out_w);
    final_kernel<<<(NGRAPH + 255) / 256, 256>>>(out_b, out);
}

// round 6
// speedup vs baseline: 1.6266x; 1.0901x over previous
#include <cuda_runtime.h>
#include <math.h>

#define NATOMS 25000
#define NEDGES 300000
#define NGRAPH 500
#define DDIM   256
#define ADIM   200
#define KEMB   224     // ADIM padded to multiple of 8 (xa rows [200,224) are zero)
#define LLAYERS 3
#define TE     32      // rows (edges/atoms) per block tile
#define NT     128     // threads per gemm block
#define PADR   36      // smem row stride (k-major): 144B; 16B-aligned row pairs

#define COEF_F ((float)(1.602176634e-19 * 1.602176634e-19 / \
                 (4.0 * 3.14159265358979323846 * 8.8541878128e-12 * 1e-10)))

// ---- scratch (static device globals; no allocation) ----
__device__ float d_dist[NEDGES];
__device__ float d_h   [NATOMS * DDIM];
__device__ float d_hsrc[NATOMS * DDIM];
__device__ float d_hdst[NATOMS * DDIM];
__device__ float d_agg [NATOMS * DDIM];
__device__ float d_pool[NGRAPH];
__device__ int   d_cnt [NGRAPH];

// ---- packed f32x2 helpers ----
__device__ __forceinline__ unsigned long long pack2f(float lo, float hi) {
    unsigned long long v;
    asm("mov.b64 %0, {%1, %2};" : "=l"(v) : "f"(lo), "f"(hi));
    return v;
}
__device__ __forceinline__ void unpack2f(unsigned long long v, float& lo, float& hi) {
    asm("mov.b64 {%0, %1}, %2;" : "=f"(lo), "=f"(hi) : "l"(v));
}
__device__ __forceinline__ void fma2(unsigned long long& a, unsigned long long x, unsigned long long w) {
    asm("fma.rn.f32x2 %0, %1, %2, %0;" : "+l"(a) : "l"(x), "l"(w));
}

__device__ __forceinline__ float softplus_f(float x) {
    return fmaxf(x, 0.0f) + __logf(1.0f + __expf(-fabsf(x)));
}
// mish(x) = x * tanh(softplus(x)) = x * (p^2-1)/(p^2+1), p = 1+e^x
__device__ __forceinline__ float mish_f(float x) {
    float ex = __expf(fminf(x, 20.0f));
    float p  = 1.0f + ex;
    float p2 = p * p;
    return x * __fdividef(p2 - 1.0f, p2 + 1.0f);
}

// ==== register-blocked tile GEMM: per thread 4 cols x 16 rows ====
// 128 threads: c0 = tid & 63 -> cols {c0, c0+64, c0+128, c0+192};
//              rg = tid >> 6 -> rows [rg*16, rg*16+16).
// acc[cc*8 + j]: col c0+64*cc, rows (rbase+2j, rbase+2j+1).
// Per k: 4x LDS.128 (broadcast) + 4x LDG(W) for 32 FFMA2  (wf/FFMA2 = 0.25).

__device__ __forceinline__ void ldw4(float w[4][4], const float* __restrict__ W,
                                     int k, int c0) {
#pragma unroll
    for (int i = 0; i < 4; i++)
#pragma unroll
        for (int cc = 0; cc < 4; cc++)
            w[i][cc] = __ldg(W + (size_t)(k + i) * DDIM + c0 + 64 * cc);
}
// Clamped variant (embed): rows >= kmax alias row kmax-1 (in-bounds; matching xs rows are zero)
__device__ __forceinline__ void ldw4c(float w[4][4], const float* __restrict__ W,
                                      int k, int c0, int kmax) {
#pragma unroll
    for (int i = 0; i < 4; i++) {
        int kk = k + i; if (kk >= kmax) kk = kmax - 1;
#pragma unroll
        for (int cc = 0; cc < 4; cc++)
            w[i][cc] = __ldg(W + (size_t)kk * DDIM + c0 + 64 * cc);
    }
}

__device__ __forceinline__ void fma4(unsigned long long acc[32], const float w[4][4],
                                     const float* __restrict__ xs) {
#pragma unroll
    for (int i = 0; i < 4; i++) {
        unsigned long long wv[4];
#pragma unroll
        for (int cc = 0; cc < 4; cc++) wv[cc] = pack2f(w[i][cc], w[i][cc]);
        const ulonglong2* xr = (const ulonglong2*)(xs + (size_t)i * PADR);
#pragma unroll
        for (int j2 = 0; j2 < 4; j2++) {
            ulonglong2 v = xr[j2];
#pragma unroll
            for (int cc = 0; cc < 4; cc++) {
                fma2(acc[cc * 8 + 2 * j2],     v.x, wv[cc]);
                fma2(acc[cc * 8 + 2 * j2 + 1], v.y, wv[cc]);
            }
        }
    }
}

// xs must point at the thread's row-group base (xa + rg*16). K % 8 == 0.
__device__ __forceinline__ void gemm4x16(const float* __restrict__ W,
                                         const float* __restrict__ xs,
                                         int K, int c0, unsigned long long acc[32]) {
#pragma unroll
    for (int j = 0; j < 32; j++) acc[j] = 0ULL;
    float wa[4][4], wb[4][4];
    ldw4(wa, W, 0, c0);
    for (int k0 = 0; k0 < K; k0 += 8) {
        int kn = (k0 + 8 < K) ? k0 + 8 : 0;
        ldw4(wb, W, k0 + 4, c0);
        fma4(acc, wa, xs + (size_t)k0 * PADR);
        ldw4(wa, W, kn, c0);
        fma4(acc, wb, xs + (size_t)(k0 + 4) * PADR);
    }
}

__device__ __forceinline__ void gemm4x16_clamp(const float* __restrict__ W,
                                               const float* __restrict__ xs,
                                               int K, int kmax, int c0,
                                               unsigned long long acc[32]) {
#pragma unroll
    for (int j = 0; j < 32; j++) acc[j] = 0ULL;
    float wa[4][4], wb[4][4];
    ldw4c(wa, W, 0, c0, kmax);
    for (int k0 = 0; k0 < K; k0 += 8) {
        int kn = (k0 + 8 < K) ? k0 + 8 : 0;
        ldw4c(wb, W, k0 + 4, c0, kmax);
        fma4(acc, wa, xs + (size_t)k0 * PADR);
        ldw4c(wa, W, kn, c0, kmax);
        fma4(acc, wb, xs + (size_t)(k0 + 4) * PADR);
    }
}

// Epilogue: bias + mish -> k-major smem tile
__device__ __forceinline__ void epi_mish_sts(float* __restrict__ xb,
                                             const unsigned long long acc[32],
                                             const float* __restrict__ bias,
                                             int c0, int rbase) {
#pragma unroll
    for (int cc = 0; cc < 4; cc++) {
        int c = c0 + 64 * cc;
        float b = bias[c];
#pragma unroll
        for (int j = 0; j < 8; j++) {
            float lo, hi; unpack2f(acc[cc * 8 + j], lo, hi);
            xb[c * PADR + rbase + 2 * j]     = mish_f(lo + b);
            xb[c * PADR + rbase + 2 * j + 1] = mish_f(hi + b);
        }
    }
}

// Epilogue: bias -> global rows (guarded)
__device__ __forceinline__ void epi_bias_stg(float* __restrict__ g,
                                             const unsigned long long acc[32],
                                             const float* __restrict__ bias,
                                             int c0, int rbase, int row0) {
#pragma unroll
    for (int cc = 0; cc < 4; cc++) {
        int c = c0 + 64 * cc;
        float b = bias[c];
#pragma unroll
        for (int j = 0; j < 8; j++) {
            float lo, hi; unpack2f(acc[cc * 8 + j], lo, hi);
            int r0 = row0 + rbase + 2 * j, r1 = r0 + 1;
            if (r0 < NATOMS) g[(size_t)r0 * DDIM + c] = lo + b;
            if (r1 < NATOMS) g[(size_t)r1 * DDIM + c] = hi + b;
        }
    }
}

// ---- small kernels ----
__global__ void __launch_bounds__(256) dist_kernel(const float* __restrict__ r) {
    int e = blockIdx.x * blockDim.x + threadIdx.x;
    if (e < NEDGES) {
        float x = r[3 * e], y = r[3 * e + 1], z = r[3 * e + 2];
        d_dist[e] = sqrtf(x * x + y * y + z * z);
    }
}

__global__ void __launch_bounds__(256) zero_pool_kernel() {
    int g = blockIdx.x * blockDim.x + threadIdx.x;
    if (g < NGRAPH) { d_pool[g] = 0.0f; d_cnt[g] = 0; }
}

// pool applies the final softplus(h + agg) itself (layer-3 epilogue fused here)
__global__ void __launch_bounds__(256) pool_kernel(const int* __restrict__ gids,
                                                   const float* __restrict__ out_w) {
    int warp = (blockIdx.x * blockDim.x + threadIdx.x) >> 5;
    int lane = threadIdx.x & 31;
    if (warp >= NATOMS) return;
    float s = 0.0f;
    for (int k = lane; k < DDIM; k += 32) {
        size_t off = (size_t)warp * DDIM + k;
        s += softplus_f(d_h[off] + d_agg[off]) * out_w[k];
    }
#pragma unroll
    for (int off = 16; off > 0; off >>= 1)
        s += __shfl_xor_sync(0xFFFFFFFFu, s, off);
    if (lane == 0) {
        atomicAdd(&d_pool[gids[warp]], s);
        atomicAdd(&d_cnt[gids[warp]], 1);
    }
}

__global__ void __launch_bounds__(256) final_kernel(const float* __restrict__ out_b,
                                                    float* __restrict__ out) {
    int g = blockIdx.x * blockDim.x + threadIdx.x;
    if (g < NGRAPH)
        out[g] = d_pool[g] / fmaxf((float)d_cnt[g], 1.0f) + out_b[0];
}

// ---- embedding: h = af_table[atom_types] @ emb_w + emb_b ----
__global__ void __launch_bounds__(NT) embed_kernel(const int* __restrict__ atom_types,
                                                   const float* __restrict__ af,
                                                   const float* __restrict__ emb_w,
                                                   const float* __restrict__ emb_b) {
    extern __shared__ float sm[];
    float* xa = sm;  // [KEMB][PADR] k-major (rows >= ADIM zero)
    __shared__ int sT[TE];
    int tid = threadIdx.x;
    int c0 = tid & 63, rg = tid >> 6, rbase = rg * 16;
    int row0 = blockIdx.x * TE;
    if (tid < TE) {
        int row = row0 + tid;
        sT[tid] = (row < NATOMS) ? atom_types[row] : 0;
    }
    __syncthreads();
    for (int idx = tid; idx < TE * KEMB; idx += NT) {
        int r = idx / KEMB, k = idx - r * KEMB;
        float v = 0.0f;
        if (k < ADIM && row0 + r < NATOMS) v = af[(size_t)sT[r] * ADIM + k];
        xa[k * PADR + r] = v;
    }
    __syncthreads();
    unsigned long long acc[32];
    gemm4x16_clamp(emb_w, xa + rbase, KEMB, ADIM, c0, acc);
    epi_bias_stg(d_h, acc, emb_b, c0, rbase, row0);
}

// ---- node kernel: softplus(h+agg) update, zero agg, then src/dst MLPs ----
__global__ void __launch_bounds__(NT) node_kernel(
    int use_agg,
    const float* __restrict__ W1s, const float* __restrict__ b1s,
    const float* __restrict__ W2s, const float* __restrict__ b2s,
    const float* __restrict__ W1d, const float* __restrict__ b1d,
    const float* __restrict__ W2d, const float* __restrict__ b2d) {
    extern __shared__ float sm[];
    float* xa = sm;                 // input tile   [256][PADR]
    float* xb = sm + DDIM * PADR;   // hidden tile  [256][PADR]
    int tid = threadIdx.x;
    int c0 = tid & 63, rg = tid >> 6, rbase = rg * 16;
    int row0 = blockIdx.x * TE;
    for (int idx = tid; idx < TE * DDIM; idx += NT) {
        int r = idx >> 8, k = idx & 255;
        int row = row0 + r;
        float v = 0.0f;
        if (row < NATOMS) {
            size_t off = (size_t)row * DDIM + k;
            if (use_agg) {
                v = softplus_f(d_h[off] + d_agg[off]);
                d_h[off] = v;          // persist updated h for next layer / pool
            } else {
                v = d_h[off];
            }
            d_agg[off] = 0.0f;         // ready for this layer's edge atomics
        }
        xa[k * PADR + r] = v;
    }
    __syncthreads();
    unsigned long long acc[32];

    // src branch
    gemm4x16(W1s, xa + rbase, DDIM, c0, acc);
    epi_mish_sts(xb, acc, b1s, c0, rbase);
    __syncthreads();
    gemm4x16(W2s, xb + rbase, DDIM, c0, acc);
    epi_bias_stg(d_hsrc, acc, b2s, c0, rbase, row0);
    __syncthreads();

    // dst branch (xa still intact)
    gemm4x16(W1d, xa + rbase, DDIM, c0, acc);
    epi_mish_sts(xb, acc, b1d, c0, rbase);
    __syncthreads();
    gemm4x16(W2d, xb + rbase, DDIM, c0, acc);
    epi_bias_stg(d_hdst, acc, b2d, c0, rbase, row0);
}

// ---- fused edge kernel: RBF -> edge MLP -> Coulomb combine -> m MLP -> atomic agg ----
__global__ void __launch_bounds__(NT) edge_kernel(
    const int* __restrict__ esrc, const int* __restrict__ edst,
    const float* __restrict__ W1e, const float* __restrict__ b1e,
    const float* __restrict__ W2e, const float* __restrict__ b2e,
    const float* __restrict__ W1m, const float* __restrict__ b1m,
    const float* __restrict__ W2m, const float* __restrict__ b2m) {
    extern __shared__ float sm[];
    float* xa = sm;
    float* xb = sm + DDIM * PADR;
    __shared__ int   sSrc[TE], sDst[TE];
    __shared__ float sDist[TE];
    int tid = threadIdx.x;
    int c0 = tid & 63, rg = tid >> 6, rbase = rg * 16;
    int e0 = blockIdx.x * TE;
    if (tid < TE) {
        sSrc[tid]  = esrc[e0 + tid];
        sDst[tid]  = edst[e0 + tid];
        sDist[tid] = d_dist[e0 + tid];
    }
    __syncthreads();

    // RBF expansion into xa: thread fills cols {tid, tid+128} for all 32 rows
    {
        float c1 = (float)tid * (1.0f / 255.0f);
        float c2 = (float)(tid + 128) * (1.0f / 255.0f);
#pragma unroll
        for (int r = 0; r < TE; r++) {
            float dd = sDist[r];
            float t1 = dd - c1, t2 = dd - c2;
            xa[tid * PADR + r]         = __expf(-255.0f * t1 * t1);
            xa[(tid + 128) * PADR + r] = __expf(-255.0f * t2 * t2);
        }
    }
    __syncthreads();

    unsigned long long acc[32];

    gemm4x16(W1e, xa + rbase, DDIM, c0, acc);
    epi_mish_sts(xb, acc, b1e, c0, rbase);
    __syncthreads();

    gemm4x16(W2e, xb + rbase, DDIM, c0, acc);
    {
#pragma unroll
        for (int cc = 0; cc < 4; cc++) {
            int c = c0 + 64 * cc;
            float b = b2e[c];
#pragma unroll
            for (int j = 0; j < 8; j++) {
                float lo, hi; unpack2f(acc[cc * 8 + j], lo, hi);
                int r0 = rbase + 2 * j, r1 = r0 + 1;
                int s0 = sSrc[r0], s1 = sSrc[r1], t0 = sDst[r0], t1 = sDst[r1];
                xa[c * PADR + r0] = __fdividef(
                    d_hsrc[(size_t)s0 * DDIM + c] * d_hdst[(size_t)t0 * DDIM + c] * COEF_F, lo + b);
                xa[c * PADR + r1] = __fdividef(
                    d_hsrc[(size_t)s1 * DDIM + c] * d_hdst[(size_t)t1 * DDIM + c] * COEF_F, hi + b);
            }
        }
    }
    __syncthreads();

    gemm4x16(W1m, xa + rbase, DDIM, c0, acc);
    epi_mish_sts(xb, acc, b1m, c0, rbase);
    __syncthreads();

    gemm4x16(W2m, xb + rbase, DDIM, c0, acc);
    {
#pragma unroll
        for (int cc = 0; cc < 4; cc++) {
            int c = c0 + 64 * cc;
            float b = b2m[c];
#pragma unroll
            for (int j = 0; j < 8; j++) {
                float lo, hi; unpack2f(acc[cc * 8 + j], lo, hi);
                int r0 = rbase + 2 * j, r1 = r0 + 1;
                atomicAdd(&d_agg[(size_t)sDst[r0] * DDIM + c], lo + b);
                atomicAdd(&d_agg[(size_t)sDst[r1] * DDIM + c], hi + b);
            }
        }
    }
}

extern "C" void kernel_launch(void* const* d_in, const int* in_sizes, int n_in,
                              void* d_out, int out_size) {
    const int*   atom_types = (const int*)  d_in[0];
    const int*   esrc       = (const int*)  d_in[1];
    const int*   edst       = (const int*)  d_in[2];
    const int*   gids       = (const int*)  d_in[3];
    const float* r          = (const float*)d_in[4];
    const float* af         = (const float*)d_in[5];
    const float* emb_w      = (const float*)d_in[6];
    const float* emb_b      = (const float*)d_in[7];
    const float* cw1        = (const float*)d_in[8];
    const float* cb1        = (const float*)d_in[9];
    const float* cw2        = (const float*)d_in[10];
    const float* cb2        = (const float*)d_in[11];
    const float* out_w      = (const float*)d_in[12];
    const float* out_b      = (const float*)d_in[13];
    float* out = (float*)d_out;

    const int SMEM_BIG   = 2 * DDIM * PADR * 4;   // 73728 B
    const int SMEM_EMBED = KEMB * PADR * 4;
    cudaFuncSetAttribute(edge_kernel,  cudaFuncAttributeMaxDynamicSharedMemorySize, SMEM_BIG);
    cudaFuncSetAttribute(node_kernel,  cudaFuncAttributeMaxDynamicSharedMemorySize, SMEM_BIG);
    cudaFuncSetAttribute(embed_kernel, cudaFuncAttributeMaxDynamicSharedMemorySize, SMEM_EMBED);

    dist_kernel<<<(NEDGES + 255) / 256, 256>>>(r);
    embed_kernel<<<(NATOMS + TE - 1) / TE, NT, SMEM_EMBED>>>(atom_types, af, emb_w, emb_b);

    const size_t MM = (size_t)DDIM * DDIM;
    for (int l = 0; l < LLAYERS; l++) {
        const float* W1 = cw1 + (size_t)l * 4 * MM;
        const float* B1 = cb1 + (size_t)l * 4 * DDIM;
        const float* W2 = cw2 + (size_t)l * 4 * MM;
        const float* B2 = cb2 + (size_t)l * 4 * DDIM;

        node_kernel<<<(NATOMS + TE - 1) / TE, NT, SMEM_BIG>>>(
            l > 0 ? 1 : 0,
            W1 + 0 * MM, B1 + 0 * DDIM, W2 + 0 * MM, B2 + 0 * DDIM,
            W1 + 1 * MM, B1 + 1 * DDIM, W2 + 1 * MM, B2 + 1 * DDIM);

        edge_kernel<<<NEDGES / TE, NT, SMEM_BIG>>>(
            esrc, edst,
            W1 + 2 * MM, B1 + 2 * DDIM, W2 + 2 * MM, B2 + 2 * DDIM,
            W1 + 3 * MM, B1 + 3 * DDIM, W2 + 3 * MM, B2 + 3 * DDIM);
    }

    zero_pool_kernel<<<(NGRAPH + 255) / 256, 256>>>();
    pool_kernel<<<(NATOMS * 32 + 255) / 256, 256>>>(gids, out_w);
    final_kernel<<<(NGRAPH + 255) / 256, 256>>>(out_b, out);
}

// round 7
// speedup vs baseline: 1.7429x; 1.0715x over previous
#include <cuda_runtime.h>
#include <math.h>

#define NATOMS 25000
#define NEDGES 300000
#define NGRAPH 500
#define DDIM   256
#define ADIM   200
#define KEMB   224     // ADIM padded to multiple of 8 (xa rows [200,224) are zero)
#define LLAYERS 3
#define TE     32      // rows (edges/atoms) per block tile
#define NT     128     // threads per gemm block
#define PADR   36      // smem row stride (k-major): 144B; 16B-aligned row groups

#define COEF_F ((float)(1.602176634e-19 * 1.602176634e-19 / \
                 (4.0 * 3.14159265358979323846 * 8.8541878128e-12 * 1e-10)))

typedef unsigned long long u64;

// ---- scratch (static device globals; no allocation) ----
__device__ float d_dist[NEDGES];
__device__ float d_h   [NATOMS * DDIM];
__device__ float d_hsrc[NATOMS * DDIM];
__device__ float d_hdst[NATOMS * DDIM];
__device__ float d_agg [NATOMS * DDIM];
__device__ float d_pool[NGRAPH];
__device__ int   d_cnt [NGRAPH];

// ---- packed f32x2 helpers ----
__device__ __forceinline__ u64 pack2f(float lo, float hi) {
    u64 v;
    asm("mov.b64 %0, {%1, %2};" : "=l"(v) : "f"(lo), "f"(hi));
    return v;
}
__device__ __forceinline__ void unpack2f(u64 v, float& lo, float& hi) {
    asm("mov.b64 {%0, %1}, %2;" : "=f"(lo), "=f"(hi) : "l"(v));
}
__device__ __forceinline__ void fma2(u64& a, u64 x, u64 w) {
    asm("fma.rn.f32x2 %0, %1, %2, %0;" : "+l"(a) : "l"(x), "l"(w));
}
// vector atomic add (no return)
__device__ __forceinline__ void red2(float* p, float a, float b) {
    asm volatile("red.global.add.v2.f32 [%0], {%1, %2};" :: "l"(p), "f"(a), "f"(b) : "memory");
}

__device__ __forceinline__ float softplus_f(float x) {
    return fmaxf(x, 0.0f) + __logf(1.0f + __expf(-fabsf(x)));
}
// mish(x) = x * tanh(softplus(x)) = x * (p^2-1)/(p^2+1), p = 1+e^x
__device__ __forceinline__ float mish_f(float x) {
    float ex = __expf(fminf(x, 20.0f));
    float p  = 1.0f + ex;
    float p2 = p * p;
    return x * __fdividef(p2 - 1.0f, p2 + 1.0f);
}

// ==== register-blocked tile GEMM: per thread 4 cols x 16 rows, xs double-buffered ====
// 128 threads: cp = tid & 63 -> cols {2cp, 2cp+1, 2cp+128, 2cp+129};
//              rg = tid >> 6 -> rows [rg*16, rg*16+16).
// acc[ 0+j]: col 2cp      rows (2j,2j+1)   (j = 0..7)
// acc[ 8+j]: col 2cp+1
// acc[16+j]: col 2cp+128
// acc[24+j]: col 2cp+129
// Per k: 4x LDS.128 (prefetched 1 k ahead) + 2x LDG.64 (batched 4-8 ahead) + 32 FFMA2.

__device__ __forceinline__ void ldw4(float2 w[4][2], const float* __restrict__ W,
                                     int k, int cp) {
#pragma unroll
    for (int i = 0; i < 4; i++) {
        w[i][0] = *(const float2*)(W + (size_t)(k + i) * DDIM + 2 * cp);
        w[i][1] = *(const float2*)(W + (size_t)(k + i) * DDIM + 2 * cp + 128);
    }
}
// Clamped variant (embed): rows >= kmax alias row kmax-1 (in-bounds; matching xs rows are zero)
__device__ __forceinline__ void ldw4c(float2 w[4][2], const float* __restrict__ W,
                                      int k, int cp, int kmax) {
#pragma unroll
    for (int i = 0; i < 4; i++) {
        int kk = k + i; if (kk >= kmax) kk = kmax - 1;
        w[i][0] = *(const float2*)(W + (size_t)kk * DDIM + 2 * cp);
        w[i][1] = *(const float2*)(W + (size_t)kk * DDIM + 2 * cp + 128);
    }
}

__device__ __forceinline__ void ldx(ulonglong2 cur[4], const float* __restrict__ xs, int k) {
    const ulonglong2* xr = (const ulonglong2*)(xs + (size_t)k * PADR);
#pragma unroll
    for (int j = 0; j < 4; j++) cur[j] = xr[j];
}

__device__ __forceinline__ void fma_k(u64 acc[32], float2 w01, float2 w23,
                                      const ulonglong2 cur[4]) {
    u64 wv0 = pack2f(w01.x, w01.x);
    u64 wv1 = pack2f(w01.y, w01.y);
    u64 wv2 = pack2f(w23.x, w23.x);
    u64 wv3 = pack2f(w23.y, w23.y);
#pragma unroll
    for (int j2 = 0; j2 < 4; j2++) {
        u64 plo = cur[j2].x, phi = cur[j2].y;   // row pairs 2*j2, 2*j2+1
        fma2(acc[     2 * j2],     plo, wv0); fma2(acc[     2 * j2 + 1], phi, wv0);
        fma2(acc[ 8 + 2 * j2],     plo, wv1); fma2(acc[ 8 + 2 * j2 + 1], phi, wv1);
        fma2(acc[16 + 2 * j2],     plo, wv2); fma2(acc[16 + 2 * j2 + 1], phi, wv2);
        fma2(acc[24 + 2 * j2],     plo, wv3); fma2(acc[24 + 2 * j2 + 1], phi, wv3);
    }
}

// xs must point at the thread's row-group base (xa + rg*16). K % 8 == 0.
__device__ __forceinline__ void gemm4x16(const float* __restrict__ W,
                                         const float* __restrict__ xs,
                                         int K, int cp, u64 acc[32]) {
#pragma unroll
    for (int j = 0; j < 32; j++) acc[j] = 0ULL;
    float2 wa[4][2], wb[4][2];
    ulonglong2 cur[4], nxt[4];
    ldw4(wa, W, 0, cp);
    ldx(cur, xs, 0);
    for (int k0 = 0; k0 < K; k0 += 8) {
        ldw4(wb, W, k0 + 4, cp);
#pragma unroll
        for (int i = 0; i < 4; i++) {
            int kk = k0 + i + 1; if (kk >= K) kk = 0;
            ldx(nxt, xs, kk);
            fma_k(acc, wa[i][0], wa[i][1], cur);
#pragma unroll
            for (int j = 0; j < 4; j++) cur[j] = nxt[j];
        }
        ldw4(wa, W, (k0 + 8 < K) ? k0 + 8 : 0, cp);
#pragma unroll
        for (int i = 0; i < 4; i++) {
            int kk = k0 + 5 + i; if (kk >= K) kk = 0;
            ldx(nxt, xs, kk);
            fma_k(acc, wb[i][0], wb[i][1], cur);
#pragma unroll
            for (int j = 0; j < 4; j++) cur[j] = nxt[j];
        }
    }
}

__device__ __forceinline__ void gemm4x16_clamp(const float* __restrict__ W,
                                               const float* __restrict__ xs,
                                               int K, int kmax, int cp, u64 acc[32]) {
#pragma unroll
    for (int j = 0; j < 32; j++) acc[j] = 0ULL;
    float2 wa[4][2], wb[4][2];
    ulonglong2 cur[4], nxt[4];
    ldw4c(wa, W, 0, cp, kmax);
    ldx(cur, xs, 0);
    for (int k0 = 0; k0 < K; k0 += 8) {
        ldw4c(wb, W, k0 + 4, cp, kmax);
#pragma unroll
        for (int i = 0; i < 4; i++) {
            int kk = k0 + i + 1; if (kk >= K) kk = 0;
            ldx(nxt, xs, kk);
            fma_k(acc, wa[i][0], wa[i][1], cur);
#pragma unroll
            for (int j = 0; j < 4; j++) cur[j] = nxt[j];
        }
        ldw4c(wa, W, (k0 + 8 < K) ? k0 + 8 : 0, cp, kmax);
#pragma unroll
        for (int i = 0; i < 4; i++) {
            int kk = k0 + 5 + i; if (kk >= K) kk = 0;
            ldx(nxt, xs, kk);
            fma_k(acc, wb[i][0], wb[i][1], cur);
#pragma unroll
            for (int j = 0; j < 4; j++) cur[j] = nxt[j];
        }
    }
}

// Epilogue: bias + mish -> k-major smem tile
__device__ __forceinline__ void epi_mish_sts(float* __restrict__ xb, const u64 acc[32],
                                             const float* __restrict__ bias,
                                             int cp, int rbase) {
    float2 b01 = *(const float2*)(bias + 2 * cp);
    float2 b23 = *(const float2*)(bias + 2 * cp + 128);
    int cols[4] = {2 * cp, 2 * cp + 1, 2 * cp + 128, 2 * cp + 129};
    float bs[4] = {b01.x, b01.y, b23.x, b23.y};
#pragma unroll
    for (int s = 0; s < 4; s++) {
        int c = cols[s]; float b = bs[s];
#pragma unroll
        for (int j = 0; j < 8; j++) {
            float lo, hi; unpack2f(acc[8 * s + j], lo, hi);
            xb[c * PADR + rbase + 2 * j]     = mish_f(lo + b);
            xb[c * PADR + rbase + 2 * j + 1] = mish_f(hi + b);
        }
    }
}

// Epilogue: bias -> global rows (guarded), float2 stores
__device__ __forceinline__ void epi_bias_stg(float* __restrict__ g, const u64 acc[32],
                                             const float* __restrict__ bias,
                                             int cp, int rbase, int row0) {
    float2 b01 = *(const float2*)(bias + 2 * cp);
    float2 b23 = *(const float2*)(bias + 2 * cp + 128);
#pragma unroll
    for (int j = 0; j < 8; j++) {
        float lo0, hi0, lo1, hi1, lo2, hi2, lo3, hi3;
        unpack2f(acc[j],      lo0, hi0);
        unpack2f(acc[8 + j],  lo1, hi1);
        unpack2f(acc[16 + j], lo2, hi2);
        unpack2f(acc[24 + j], lo3, hi3);
        int r0 = row0 + rbase + 2 * j, r1 = r0 + 1;
        if (r0 < NATOMS) {
            *(float2*)(g + (size_t)r0 * DDIM + 2 * cp)       = make_float2(lo0 + b01.x, lo1 + b01.y);
            *(float2*)(g + (size_t)r0 * DDIM + 2 * cp + 128) = make_float2(lo2 + b23.x, lo3 + b23.y);
        }
        if (r1 < NATOMS) {
            *(float2*)(g + (size_t)r1 * DDIM + 2 * cp)       = make_float2(hi0 + b01.x, hi1 + b01.y);
            *(float2*)(g + (size_t)r1 * DDIM + 2 * cp + 128) = make_float2(hi2 + b23.x, hi3 + b23.y);
        }
    }
}

// ---- small kernels ----
__global__ void __launch_bounds__(256) dist_kernel(const float* __restrict__ r) {
    int e = blockIdx.x * blockDim.x + threadIdx.x;
    if (e < NEDGES) {
        float x = r[3 * e], y = r[3 * e + 1], z = r[3 * e + 2];
        d_dist[e] = sqrtf(x * x + y * y + z * z);
    }
}

__global__ void __launch_bounds__(256) zero_pool_kernel() {
    int g = blockIdx.x * blockDim.x + threadIdx.x;
    if (g < NGRAPH) { d_pool[g] = 0.0f; d_cnt[g] = 0; }
}

// pool applies the final softplus(h + agg) itself (layer-3 epilogue fused here)
__global__ void __launch_bounds__(256) pool_kernel(const int* __restrict__ gids,
                                                   const float* __restrict__ out_w) {
    int warp = (blockIdx.x * blockDim.x + threadIdx.x) >> 5;
    int lane = threadIdx.x & 31;
    if (warp >= NATOMS) return;
    float s = 0.0f;
    for (int k = lane; k < DDIM; k += 32) {
        size_t off = (size_t)warp * DDIM + k;
        s += softplus_f(d_h[off] + d_agg[off]) * out_w[k];
    }
#pragma unroll
    for (int off = 16; off > 0; off >>= 1)
        s += __shfl_xor_sync(0xFFFFFFFFu, s, off);
    if (lane == 0) {
        atomicAdd(&d_pool[gids[warp]], s);
        atomicAdd(&d_cnt[gids[warp]], 1);
    }
}

__global__ void __launch_bounds__(256) final_kernel(const float* __restrict__ out_b,
                                                    float* __restrict__ out) {
    int g = blockIdx.x * blockDim.x + threadIdx.x;
    if (g < NGRAPH)
        out[g] = d_pool[g] / fmaxf((float)d_cnt[g], 1.0f) + out_b[0];
}

// ---- embedding: h = af_table[atom_types] @ emb_w + emb_b ----
__global__ void __launch_bounds__(NT) embed_kernel(const int* __restrict__ atom_types,
                                                   const float* __restrict__ af,
                                                   const float* __restrict__ emb_w,
                                                   const float* __restrict__ emb_b) {
    extern __shared__ float sm[];
    float* xa = sm;  // [KEMB][PADR] k-major (rows >= ADIM zero)
    __shared__ int sT[TE];
    int tid = threadIdx.x;
    int cp = tid & 63, rg = tid >> 6, rbase = rg * 16;
    int row0 = blockIdx.x * TE;
    if (tid < TE) {
        int row = row0 + tid;
        sT[tid] = (row < NATOMS) ? atom_types[row] : 0;
    }
    __syncthreads();
    for (int idx = tid; idx < TE * KEMB; idx += NT) {
        int r = idx / KEMB, k = idx - r * KEMB;
        float v = 0.0f;
        if (k < ADIM && row0 + r < NATOMS) v = af[(size_t)sT[r] * ADIM + k];
        xa[k * PADR + r] = v;
    }
    __syncthreads();
    u64 acc[32];
    gemm4x16_clamp(emb_w, xa + rbase, KEMB, ADIM, cp, acc);
    epi_bias_stg(d_h, acc, emb_b, cp, rbase, row0);
}

// ---- node kernel: softplus(h+agg) update, zero agg, then src/dst MLPs ----
__global__ void __launch_bounds__(NT, 3) node_kernel(
    int use_agg,
    const float* __restrict__ W1s, const float* __restrict__ b1s,
    const float* __restrict__ W2s, const float* __restrict__ b2s,
    const float* __restrict__ W1d, const float* __restrict__ b1d,
    const float* __restrict__ W2d, const float* __restrict__ b2d) {
    extern __shared__ float sm[];
    float* xa = sm;                 // input tile   [256][PADR]
    float* xb = sm + DDIM * PADR;   // hidden tile  [256][PADR]
    int tid = threadIdx.x;
    int cp = tid & 63, rg = tid >> 6, rbase = rg * 16;
    int row0 = blockIdx.x * TE;
    for (int idx = tid; idx < TE * DDIM; idx += NT) {
        int r = idx >> 8, k = idx & 255;
        int row = row0 + r;
        float v = 0.0f;
        if (row < NATOMS) {
            size_t off = (size_t)row * DDIM + k;
            if (use_agg) {
                v = softplus_f(d_h[off] + d_agg[off]);
                d_h[off] = v;          // persist updated h for next layer / pool
            } else {
                v = d_h[off];
            }
            d_agg[off] = 0.0f;         // ready for this layer's edge atomics
        }
        xa[k * PADR + r] = v;
    }
    __syncthreads();
    u64 acc[32];

    // src branch
    gemm4x16(W1s, xa + rbase, DDIM, cp, acc);
    epi_mish_sts(xb, acc, b1s, cp, rbase);
    __syncthreads();
    gemm4x16(W2s, xb + rbase, DDIM, cp, acc);
    epi_bias_stg(d_hsrc, acc, b2s, cp, rbase, row0);
    __syncthreads();

    // dst branch (xa still intact)
    gemm4x16(W1d, xa + rbase, DDIM, cp, acc);
    epi_mish_sts(xb, acc, b1d, cp, rbase);
    __syncthreads();
    gemm4x16(W2d, xb + rbase, DDIM, cp, acc);
    epi_bias_stg(d_hdst, acc, b2d, cp, rbase, row0);
}

// ---- fused edge kernel: RBF -> edge MLP -> Coulomb combine -> m MLP -> atomic agg ----
__global__ void __launch_bounds__(NT, 3) edge_kernel(
    const int* __restrict__ esrc, const int* __restrict__ edst,
    const float* __restrict__ W1e, const float* __restrict__ b1e,
    const float* __restrict__ W2e, const float* __restrict__ b2e,
    const float* __restrict__ W1m, const float* __restrict__ b1m,
    const float* __restrict__ W2m, const float* __restrict__ b2m) {
    extern __shared__ float sm[];
    float* xa = sm;
    float* xb = sm + DDIM * PADR;
    __shared__ int   sSrc[TE], sDst[TE];
    __shared__ float sDist[TE];
    int tid = threadIdx.x;
    int cp = tid & 63, rg = tid >> 6, rbase = rg * 16;
    int e0 = blockIdx.x * TE;
    if (tid < TE) {
        sSrc[tid]  = esrc[e0 + tid];
        sDst[tid]  = edst[e0 + tid];
        sDist[tid] = d_dist[e0 + tid];
    }
    __syncthreads();

    // RBF expansion into xa: thread fills cols {tid, tid+128} for all 32 rows
    {
        float c1 = (float)tid * (1.0f / 255.0f);
        float c2 = (float)(tid + 128) * (1.0f / 255.0f);
#pragma unroll
        for (int r = 0; r < TE; r++) {
            float dd = sDist[r];
            float t1 = dd - c1, t2 = dd - c2;
            xa[tid * PADR + r]         = __expf(-255.0f * t1 * t1);
            xa[(tid + 128) * PADR + r] = __expf(-255.0f * t2 * t2);
        }
    }
    __syncthreads();

    u64 acc[32];

    gemm4x16(W1e, xa + rbase, DDIM, cp, acc);
    epi_mish_sts(xb, acc, b1e, cp, rbase);
    __syncthreads();

    gemm4x16(W2e, xb + rbase, DDIM, cp, acc);
    {
        float2 b01 = *(const float2*)(b2e + 2 * cp);
        float2 b23 = *(const float2*)(b2e + 2 * cp + 128);
#pragma unroll
        for (int j = 0; j < 8; j++) {
            int r0 = rbase + 2 * j, r1 = r0 + 1;
            int s0 = sSrc[r0], s1 = sSrc[r1], t0 = sDst[r0], t1 = sDst[r1];
            float lo0, hi0, lo1, hi1, lo2, hi2, lo3, hi3;
            unpack2f(acc[j],      lo0, hi0);
            unpack2f(acc[8 + j],  lo1, hi1);
            unpack2f(acc[16 + j], lo2, hi2);
            unpack2f(acc[24 + j], lo3, hi3);
            // row r0 gathers
            float2 hsA = *(const float2*)(d_hsrc + (size_t)s0 * DDIM + 2 * cp);
            float2 hdA = *(const float2*)(d_hdst + (size_t)t0 * DDIM + 2 * cp);
            float2 hsB = *(const float2*)(d_hsrc + (size_t)s0 * DDIM + 2 * cp + 128);
            float2 hdB = *(const float2*)(d_hdst + (size_t)t0 * DDIM + 2 * cp + 128);
            xa[(2 * cp) * PADR + r0]       = __fdividef(hsA.x * hdA.x * COEF_F, lo0 + b01.x);
            xa[(2 * cp + 1) * PADR + r0]   = __fdividef(hsA.y * hdA.y * COEF_F, lo1 + b01.y);
            xa[(2 * cp + 128) * PADR + r0] = __fdividef(hsB.x * hdB.x * COEF_F, lo2 + b23.x);
            xa[(2 * cp + 129) * PADR + r0] = __fdividef(hsB.y * hdB.y * COEF_F, lo3 + b23.y);
            // row r1 gathers
            hsA = *(const float2*)(d_hsrc + (size_t)s1 * DDIM + 2 * cp);
            hdA = *(const float2*)(d_hdst + (size_t)t1 * DDIM + 2 * cp);
            hsB = *(const float2*)(d_hsrc + (size_t)s1 * DDIM + 2 * cp + 128);
            hdB = *(const float2*)(d_hdst + (size_t)t1 * DDIM + 2 * cp + 128);
            xa[(2 * cp) * PADR + r1]       = __fdividef(hsA.x * hdA.x * COEF_F, hi0 + b01.x);
            xa[(2 * cp + 1) * PADR + r1]   = __fdividef(hsA.y * hdA.y * COEF_F, hi1 + b01.y);
            xa[(2 * cp + 128) * PADR + r1] = __fdividef(hsB.x * hdB.x * COEF_F, hi2 + b23.x);
            xa[(2 * cp + 129) * PADR + r1] = __fdividef(hsB.y * hdB.y * COEF_F, hi3 + b23.y);
        }
    }
    __syncthreads();

    gemm4x16(W1m, xa + rbase, DDIM, cp, acc);
    epi_mish_sts(xb, acc, b1m, cp, rbase);
    __syncthreads();

    gemm4x16(W2m, xb + rbase, DDIM, cp, acc);
    {
        float2 b01 = *(const float2*)(b2m + 2 * cp);
        float2 b23 = *(const float2*)(b2m + 2 * cp + 128);
#pragma unroll
        for (int j = 0; j < 8; j++) {
            int r0 = rbase + 2 * j, r1 = r0 + 1;
            int t0 = sDst[r0], t1 = sDst[r1];
            float lo0, hi0, lo1, hi1, lo2, hi2, lo3, hi3;
            unpack2f(acc[j],      lo0, hi0);
            unpack2f(acc[8 + j],  lo1, hi1);
            unpack2f(acc[16 + j], lo2, hi2);
            unpack2f(acc[24 + j], lo3, hi3);
            red2(d_agg + (size_t)t0 * DDIM + 2 * cp,       lo0 + b01.x, lo1 + b01.y);
            red2(d_agg + (size_t)t0 * DDIM + 2 * cp + 128, lo2 + b23.x, lo3 + b23.y);
            red2(d_agg + (size_t)t1 * DDIM + 2 * cp,       hi0 + b01.x, hi1 + b01.y);
            red2(d_agg + (size_t)t1 * DDIM + 2 * cp + 128, hi2 + b23.x, hi3 + b23.y);
        }
    }
}

extern "C" void kernel_launch(void* const* d_in, const int* in_sizes, int n_in,
                              void* d_out, int out_size) {
    const int*   atom_types = (const int*)  d_in[0];
    const int*   esrc       = (const int*)  d_in[1];
    const int*   edst       = (const int*)  d_in[2];
    const int*   gids       = (const int*)  d_in[3];
    const float* r          = (const float*)d_in[4];
    const float* af         = (const float*)d_in[5];
    const float* emb_w      = (const float*)d_in[6];
    const float* emb_b      = (const float*)d_in[7];
    const float* cw1        = (const float*)d_in[8];
    const float* cb1        = (const float*)d_in[9];
    const float* cw2        = (const float*)d_in[10];
    const float* cb2        = (const float*)d_in[11];
    const float* out_w      = (const float*)d_in[12];
    const float* out_b      = (const float*)d_in[13];
    float* out = (float*)d_out;

    const int SMEM_BIG   = 2 * DDIM * PADR * 4;   // 73728 B
    const int SMEM_EMBED = KEMB * PADR * 4;
    cudaFuncSetAttribute(edge_kernel,  cudaFuncAttributeMaxDynamicSharedMemorySize, SMEM_BIG);
    cudaFuncSetAttribute(node_kernel,  cudaFuncAttributeMaxDynamicSharedMemorySize, SMEM_BIG);
    cudaFuncSetAttribute(embed_kernel, cudaFuncAttributeMaxDynamicSharedMemorySize, SMEM_EMBED);

    dist_kernel<<<(NEDGES + 255) / 256, 256>>>(r);
    embed_kernel<<<(NATOMS + TE - 1) / TE, NT, SMEM_EMBED>>>(atom_types, af, emb_w, emb_b);

    const size_t MM = (size_t)DDIM * DDIM;
    for (int l = 0; l < LLAYERS; l++) {
        const float* W1 = cw1 + (size_t)l * 4 * MM;
        const float* B1 = cb1 + (size_t)l * 4 * DDIM;
        const float* W2 = cw2 + (size_t)l * 4 * MM;
        const float* B2 = cb2 + (size_t)l * 4 * DDIM;

        node_kernel<<<(NATOMS + TE - 1) / TE, NT, SMEM_BIG>>>(
            l > 0 ? 1 : 0,
            W1 + 0 * MM, B1 + 0 * DDIM, W2 + 0 * MM, B2 + 0 * DDIM,
            W1 + 1 * MM, B1 + 1 * DDIM, W2 + 1 * MM, B2 + 1 * DDIM);

        edge_kernel<<<NEDGES / TE, NT, SMEM_BIG>>>(
            esrc, edst,
            W1 + 2 * MM, B1 + 2 * DDIM, W2 + 2 * MM, B2 + 2 * DDIM,
            W1 + 3 * MM, B1 + 3 * DDIM, W2 + 3 * MM, B2 + 3 * DDIM);
    }

    zero_pool_kernel<<<(NGRAPH + 255) / 256, 256>>>();
    pool_kernel<<<(NATOMS * 32 + 255) / 256, 256>>>(gids, out_w);
    final_kernel<<<(NGRAPH + 255) / 256, 256>>>(out_b, out);
}